// round 5
// baseline (speedup 1.0000x reference)
#include <cuda_runtime.h>

#define HW    1560
#define TQ    2
#define QTOT  3120
#define KTOT  12480
#define HEADS 12
#define DH    128
#define DIM   1536

// ---------------- scratch (device globals; no allocation allowed) ----------------
__device__ float g_q[QTOT * DIM];
__device__ float g_k[KTOT * DIM];
__device__ float g_v[KTOT * DIM];
__device__ float g_attn[QTOT * DIM];

// ---------------- helpers ----------------
__device__ __forceinline__ unsigned f2tf(float f) {
    unsigned u;
    asm("cvt.rna.tf32.f32 %0, %1;" : "=r"(u) : "f"(f));
    return u;
}

__device__ __forceinline__ void mma_tf32(float* d, const unsigned* a, unsigned b0, unsigned b1) {
    asm volatile(
        "mma.sync.aligned.m16n8k8.row.col.f32.tf32.tf32.f32 "
        "{%0,%1,%2,%3}, {%4,%5,%6,%7}, {%8,%9}, {%0,%1,%2,%3};"
        : "+f"(d[0]), "+f"(d[1]), "+f"(d[2]), "+f"(d[3])
        : "r"(a[0]), "r"(a[1]), "r"(a[2]), "r"(a[3]), "r"(b0), "r"(b1));
}

__device__ __forceinline__ bool block_needed(int b, const int* __restrict__ sel) {
    return (sel[0] == b) | (sel[1] == b) | (sel[2] == b) | (sel[3] == b);
}

// ---------------- GEMM: C[M,N] = A[M,K] @ W[N,K]^T + bias[N]  (tf32 mma) ----------------
// block tile 128x128x32, 512 threads = 16 warps (4M x 4N), warp tile 32x32.
// acc = 32 regs/thread -> ~100 regs total -> full 16-warp residency (4 warps/SMSP)
// to hide LDS latency. Ping-pong double-buffered smem, one __syncthreads per k-tile.
#define GEMM_STAGE (128 * 36)
#define GEMM_SMEM  (2 * 2 * GEMM_STAGE * 4)   // 73728 bytes

__global__ __launch_bounds__(512, 1) void gemm_bias_tf32(
    const float* __restrict__ A, const float* __restrict__ W,
    const float* __restrict__ bias, float* __restrict__ C,
    int M, int N, int K, const int* __restrict__ sel)
{
    extern __shared__ unsigned gsm[];
    const int bm = blockIdx.y * 128, bn = blockIdx.x * 128;

    if (sel) {
        int b0 = bm / HW;
        int b1 = (bm + 127) / HW;
        if (!block_needed(b0, sel) && !block_needed(b1, sel)) return;
    }

    const int tid  = threadIdx.x;
    const int warp = tid >> 5, lane = tid & 31;
    const int g = lane >> 2, t4 = lane & 3;
    const int wm = warp >> 2, wn = warp & 3;

    float acc[2][4][4] = {};

    const int lc = (tid & 7) * 4;  // col within 32-wide k tile (float4)
    const int lr = tid >> 3;       // base row (0..63), rows lr, lr+64

    float4 aF[2], wF[2];
    #pragma unroll
    for (int i = 0; i < 2; i++) {
        int row = lr + 64 * i;
        long ar = bm + row;
        aF[i] = (ar < M) ? *(const float4*)(A + ar * (long)K + lc)
                         : make_float4(0.f, 0.f, 0.f, 0.f);
        wF[i] = *(const float4*)(W + (long)(bn + row) * K + lc);
    }

    // prime stage 0
    {
        unsigned* As = gsm;
        unsigned* Ws = gsm + GEMM_STAGE;
        #pragma unroll
        for (int i = 0; i < 2; i++) {
            int row = lr + 64 * i;
            *(uint4*)&As[row * 36 + lc] =
                make_uint4(f2tf(aF[i].x), f2tf(aF[i].y), f2tf(aF[i].z), f2tf(aF[i].w));
            *(uint4*)&Ws[row * 36 + lc] =
                make_uint4(f2tf(wF[i].x), f2tf(wF[i].y), f2tf(wF[i].z), f2tf(wF[i].w));
        }
    }
    __syncthreads();

    const int KT = K >> 5;
    for (int kt = 0; kt < KT; kt++) {
        const unsigned* As = gsm + (kt & 1) * 2 * GEMM_STAGE;
        const unsigned* Ws = As + GEMM_STAGE;

        // issue global loads for next tile (latency hidden under compute)
        if (kt + 1 < KT) {
            int k0 = (kt + 1) << 5;
            #pragma unroll
            for (int i = 0; i < 2; i++) {
                int row = lr + 64 * i;
                long ar = bm + row;
                aF[i] = (ar < M) ? *(const float4*)(A + ar * (long)K + k0 + lc)
                                 : make_float4(0.f, 0.f, 0.f, 0.f);
                wF[i] = *(const float4*)(W + (long)(bn + row) * K + k0 + lc);
            }
        }

        #pragma unroll
        for (int kk = 0; kk < 4; kk++) {
            const int kb = kk * 8;
            unsigned a[2][4], b[4][2];
            #pragma unroll
            for (int mt = 0; mt < 2; mt++) {
                int m = wm * 32 + mt * 16 + g;
                a[mt][0] = As[m * 36 + kb + t4];
                a[mt][1] = As[(m + 8) * 36 + kb + t4];
                a[mt][2] = As[m * 36 + kb + t4 + 4];
                a[mt][3] = As[(m + 8) * 36 + kb + t4 + 4];
            }
            #pragma unroll
            for (int nt = 0; nt < 4; nt++) {
                int n = wn * 32 + nt * 8 + g;
                b[nt][0] = Ws[n * 36 + kb + t4];
                b[nt][1] = Ws[n * 36 + kb + t4 + 4];
            }
            #pragma unroll
            for (int nt = 0; nt < 4; nt++) {
                #pragma unroll
                for (int mt = 0; mt < 2; mt++)
                    mma_tf32(acc[mt][nt], a[mt], b[nt][0], b[nt][1]);
            }
        }

        // store next tile into the other stage
        if (kt + 1 < KT) {
            unsigned* Asn = gsm + ((kt + 1) & 1) * 2 * GEMM_STAGE;
            unsigned* Wsn = Asn + GEMM_STAGE;
            #pragma unroll
            for (int i = 0; i < 2; i++) {
                int row = lr + 64 * i;
                *(uint4*)&Asn[row * 36 + lc] =
                    make_uint4(f2tf(aF[i].x), f2tf(aF[i].y), f2tf(aF[i].z), f2tf(aF[i].w));
                *(uint4*)&Wsn[row * 36 + lc] =
                    make_uint4(f2tf(wF[i].x), f2tf(wF[i].y), f2tf(wF[i].z), f2tf(wF[i].w));
            }
        }
        __syncthreads();
    }

    #pragma unroll
    for (int mt = 0; mt < 2; mt++) {
        int r = bm + wm * 32 + mt * 16 + g;
        #pragma unroll
        for (int nt = 0; nt < 4; nt++) {
            int c = bn + wn * 32 + nt * 8 + t4 * 2;
            float b0 = bias[c], b1 = bias[c + 1];
            if (r < M)
                *(float2*)(C + (long)r * N + c) =
                    make_float2(acc[mt][nt][0] + b0, acc[mt][nt][1] + b1);
            if (r + 8 < M)
                *(float2*)(C + (long)(r + 8) * N + c) =
                    make_float2(acc[mt][nt][2] + b0, acc[mt][nt][3] + b1);
        }
    }
}

// ---------------- fused RMSNorm + RoPE (in-place, one row per CTA) ----------------
__global__ __launch_bounds__(384) void rmsnorm_rope_kernel(
    float* __restrict__ x, const float* __restrict__ gamma,
    const float* __restrict__ fc, const float* __restrict__ fs,
    const int* __restrict__ sel)
{
    __shared__ float red[12];
    __shared__ float rinv_s;
    const int row = blockIdx.x, tid = threadIdx.x;

    if (sel && !block_needed(row / HW, sel)) return;

    float4 v = *(float4*)(x + (long)row * DIM + tid * 4);
    float ss = v.x * v.x + v.y * v.y + v.z * v.z + v.w * v.w;
    #pragma unroll
    for (int s = 16; s > 0; s >>= 1) ss += __shfl_xor_sync(0xffffffffu, ss, s);
    if ((tid & 31) == 0) red[tid >> 5] = ss;
    __syncthreads();
    if (tid < 32) {
        float t = (tid < 12) ? red[tid] : 0.f;
        #pragma unroll
        for (int s = 16; s > 0; s >>= 1) t += __shfl_xor_sync(0xffffffffu, t, s);
        if (tid == 0) rinv_s = rsqrtf(t * (1.0f / DIM) + 1e-5f);
    }
    __syncthreads();
    float r = rinv_s;

    float4 g4 = *(const float4*)(gamma + tid * 4);
    float x0 = v.x * r * g4.x, x1 = v.y * r * g4.y;
    float x2 = v.z * r * g4.z, x3 = v.w * r * g4.w;

    int hd = (tid * 4) & (DH - 1);
    float4 c4 = *(const float4*)(fc + (long)row * DH + hd);
    float4 s4 = *(const float4*)(fs + (long)row * DH + hd);
    float4 o;
    o.x = x0 * c4.x - x1 * s4.y;
    o.y = x0 * s4.y + x1 * c4.x;
    o.z = x2 * c4.z - x3 * s4.w;
    o.w = x2 * s4.w + x3 * c4.z;
    *(float4*)(x + (long)row * DIM + tid * 4) = o;
}

// ---------------- fused block-sparse attention ----------------
// grid (13 qblocks, TQ, HEADS), 256 threads = 8 warps (4 M x 2 N)
#define ATT_QS 0
#define ATT_KS 16896                 // 128*132
#define ATT_VS (ATT_KS + 8448)       // + 64*132
#define ATT_PS (ATT_VS + 8704)       // + 64*136
#define ATT_RS (ATT_PS + 8704)       // + 128*68
#define ATT_SMEM_WORDS (ATT_RS + 256)

__global__ __launch_bounds__(256) void attention_kernel(
    const float* __restrict__ q, const float* __restrict__ k,
    const float* __restrict__ v, const int* __restrict__ sel,
    float* __restrict__ out)
{
    extern __shared__ unsigned sm[];
    unsigned* Qs = sm + ATT_QS;
    unsigned* Ks = sm + ATT_KS;
    unsigned* Vs = sm + ATT_VS;
    unsigned* Ps = sm + ATT_PS;
    float*    RS = (float*)(sm + ATT_RS);

    const int qb = blockIdx.x, t = blockIdx.y, h = blockIdx.z;
    const int tid = threadIdx.x, warp = tid >> 5, lane = tid & 31;
    const int g = lane >> 2, t4 = lane & 3;
    const int wm = warp >> 1, wn = warp & 1;

    const float* qbase = q + (long)(t * HW) * DIM + (long)h * DH;
    {
        const int c4 = (tid & 31) * 4;
        const int lr0 = tid >> 5;
        #pragma unroll
        for (int i = 0; i < 16; i++) {
            int r = lr0 + i * 8;
            int qr = qb * 128 + r;
            float4 val = (qr < HW) ? *(const float4*)(qbase + (long)qr * DIM + c4)
                                   : make_float4(0.f, 0.f, 0.f, 0.f);
            *(uint4*)&Qs[r * 132 + c4] =
                make_uint4(f2tf(val.x), f2tf(val.y), f2tf(val.z), f2tf(val.w));
        }
    }

    float oacc[2][8][4] = {};
    float rpart[2][2] = {};

    int s0 = sel[t * 2 + 0]; if (s0 < 0) s0 = 0;
    int s1 = sel[t * 2 + 1];
    int nb = (s1 >= 0) ? 2 : 1;

    __syncthreads();

    const float SC   = 0.08838834764831843f * 1.4426950408889634f;
    const float OFFL = 12.0f * 1.4426950408889634f;

    for (int bi = 0; bi < nb; bi++) {
        int blk = (bi == 0) ? s0 : s1;
        const float* kbp = k + (long)blk * HW * DIM + (long)h * DH;
        const float* vbp = v + (long)blk * HW * DIM + (long)h * DH;

        for (int n0 = 0; n0 < HW; n0 += 64) {
            {
                const int c4 = (tid & 31) * 4;
                const int lr0 = tid >> 5;
                #pragma unroll
                for (int i = 0; i < 8; i++) {
                    int r = lr0 + i * 8;
                    int kr = n0 + r;
                    float4 kv, vv;
                    if (kr < HW) {
                        kv = *(const float4*)(kbp + (long)kr * DIM + c4);
                        vv = *(const float4*)(vbp + (long)kr * DIM + c4);
                    } else {
                        kv = make_float4(0.f, 0.f, 0.f, 0.f);
                        vv = kv;
                    }
                    *(uint4*)&Ks[r * 132 + c4] =
                        make_uint4(f2tf(kv.x), f2tf(kv.y), f2tf(kv.z), f2tf(kv.w));
                    *(uint4*)&Vs[r * 136 + c4] =
                        make_uint4(f2tf(vv.x), f2tf(vv.y), f2tf(vv.z), f2tf(vv.w));
                }
            }
            __syncthreads();

            float sacc[2][4][4] = {};
            #pragma unroll
            for (int ks = 0; ks < 16; ks++) {
                const int kb = ks * 8;
                unsigned a[2][4];
                #pragma unroll
                for (int mt = 0; mt < 2; mt++) {
                    int m = wm * 32 + mt * 16 + g;
                    a[mt][0] = Qs[m * 132 + kb + t4];
                    a[mt][1] = Qs[(m + 8) * 132 + kb + t4];
                    a[mt][2] = Qs[m * 132 + kb + t4 + 4];
                    a[mt][3] = Qs[(m + 8) * 132 + kb + t4 + 4];
                }
                #pragma unroll
                for (int nt = 0; nt < 4; nt++) {
                    int n = wn * 32 + nt * 8 + g;
                    unsigned b0 = Ks[n * 132 + kb + t4];
                    unsigned b1 = Ks[n * 132 + kb + t4 + 4];
                    mma_tf32(sacc[0][nt], a[0], b0, b1);
                    mma_tf32(sacc[1][nt], a[1], b0, b1);
                }
            }

            #pragma unroll
            for (int mt = 0; mt < 2; mt++) {
                int rg = wm * 32 + mt * 16 + g;
                #pragma unroll
                for (int nt = 0; nt < 4; nt++) {
                    int cn = wn * 32 + nt * 8 + 2 * t4;
                    bool v0 = (n0 + cn) < HW, v1 = (n0 + cn + 1) < HW;
                    float p0 = v0 ? exp2f(fmaf(sacc[mt][nt][0], SC, -OFFL)) : 0.f;
                    float p1 = v1 ? exp2f(fmaf(sacc[mt][nt][1], SC, -OFFL)) : 0.f;
                    float p2 = v0 ? exp2f(fmaf(sacc[mt][nt][2], SC, -OFFL)) : 0.f;
                    float p3 = v1 ? exp2f(fmaf(sacc[mt][nt][3], SC, -OFFL)) : 0.f;
                    rpart[mt][0] += p0 + p1;
                    rpart[mt][1] += p2 + p3;
                    *(uint2*)&Ps[rg * 68 + cn]       = make_uint2(f2tf(p0), f2tf(p1));
                    *(uint2*)&Ps[(rg + 8) * 68 + cn] = make_uint2(f2tf(p2), f2tf(p3));
                }
            }
            // only the 2 warps sharing this wm row-group exchange P columns
            asm volatile("bar.sync %0, %1;" :: "r"(wm + 1), "r"(64) : "memory");

            #pragma unroll
            for (int ks = 0; ks < 8; ks++) {
                const int kb = ks * 8;
                unsigned a[2][4];
                #pragma unroll
                for (int mt = 0; mt < 2; mt++) {
                    int m = wm * 32 + mt * 16 + g;
                    a[mt][0] = Ps[m * 68 + kb + t4];
                    a[mt][1] = Ps[(m + 8) * 68 + kb + t4];
                    a[mt][2] = Ps[m * 68 + kb + t4 + 4];
                    a[mt][3] = Ps[(m + 8) * 68 + kb + t4 + 4];
                }
                #pragma unroll
                for (int nt = 0; nt < 8; nt++) {
                    int d = wn * 64 + nt * 8 + g;
                    unsigned b0 = Vs[(kb + t4) * 136 + d];
                    unsigned b1 = Vs[(kb + t4 + 4) * 136 + d];
                    mma_tf32(oacc[0][nt], a[0], b0, b1);
                    mma_tf32(oacc[1][nt], a[1], b0, b1);
                }
            }
            __syncthreads();
        }
    }

    #pragma unroll
    for (int mt = 0; mt < 2; mt++) {
        #pragma unroll
        for (int hh = 0; hh < 2; hh++) {
            float s = rpart[mt][hh];
            s += __shfl_xor_sync(0xffffffffu, s, 1);
            s += __shfl_xor_sync(0xffffffffu, s, 2);
            if (t4 == 0) RS[(wm * 32 + mt * 16 + hh * 8 + g) * 2 + wn] = s;
        }
    }
    __syncthreads();

    float* obase = out + (long)(t * HW) * DIM + h * DH;
    #pragma unroll
    for (int mt = 0; mt < 2; mt++) {
        int r = wm * 32 + mt * 16 + g;
        float inv0 = 1.f / (RS[r * 2] + RS[r * 2 + 1]);
        float inv1 = 1.f / (RS[(r + 8) * 2] + RS[(r + 8) * 2 + 1]);
        int qr0 = qb * 128 + r, qr1 = qr0 + 8;
        #pragma unroll
        for (int nt = 0; nt < 8; nt++) {
            int d = wn * 64 + nt * 8 + 2 * t4;
            if (qr0 < HW)
                *(float2*)(obase + (long)qr0 * DIM + d) =
                    make_float2(oacc[mt][nt][0] * inv0, oacc[mt][nt][1] * inv0);
            if (qr1 < HW)
                *(float2*)(obase + (long)qr1 * DIM + d) =
                    make_float2(oacc[mt][nt][2] * inv1, oacc[mt][nt][3] * inv1);
        }
    }
}

// ---------------- launch ----------------
extern "C" void kernel_launch(void* const* d_in, const int* in_sizes, int n_in,
                              void* d_out, int out_size)
{
    const float* hidden  = (const float*)d_in[0];
    const float* history = (const float*)d_in[1];
    const float* fc   = (const float*)d_in[2];
    const float* fs   = (const float*)d_in[3];
    const float* fch  = (const float*)d_in[4];
    const float* fsh  = (const float*)d_in[5];
    const int*   sel  = (const int*)d_in[6];
    const float* Wq = (const float*)d_in[7];
    const float* bq = (const float*)d_in[8];
    const float* Wk = (const float*)d_in[9];
    const float* bk = (const float*)d_in[10];
    const float* Wv = (const float*)d_in[11];
    const float* bv = (const float*)d_in[12];
    const float* Wo = (const float*)d_in[13];
    const float* bo = (const float*)d_in[14];
    const float* gq = (const float*)d_in[15];
    const float* gk = (const float*)d_in[16];
    float* outp = (float*)d_out;

    float *qp, *kp, *vp, *ap;
    cudaGetSymbolAddress((void**)&qp, g_q);
    cudaGetSymbolAddress((void**)&kp, g_k);
    cudaGetSymbolAddress((void**)&vp, g_v);
    cudaGetSymbolAddress((void**)&ap, g_attn);

    cudaFuncSetAttribute(gemm_bias_tf32,
                         cudaFuncAttributeMaxDynamicSharedMemorySize, GEMM_SMEM);
    cudaFuncSetAttribute(attention_kernel,
                         cudaFuncAttributeMaxDynamicSharedMemorySize, ATT_SMEM_WORDS * 4);

    gemm_bias_tf32<<<dim3(12, 25), 512, GEMM_SMEM>>>(hidden,  Wq, bq, qp, QTOT, DIM, DIM, nullptr);
    gemm_bias_tf32<<<dim3(12, 98), 512, GEMM_SMEM>>>(history, Wk, bk, kp, KTOT, DIM, DIM, sel);
    gemm_bias_tf32<<<dim3(12, 98), 512, GEMM_SMEM>>>(history, Wv, bv, vp, KTOT, DIM, DIM, sel);
    rmsnorm_rope_kernel<<<QTOT, 384>>>(qp, gq, fc, fs, nullptr);
    rmsnorm_rope_kernel<<<KTOT, 384>>>(kp, gk, fch, fsh, sel);
    attention_kernel<<<dim3(13, TQ, HEADS), 256, ATT_SMEM_WORDS * 4>>>(qp, kp, vp, sel, ap);
    gemm_bias_tf32<<<dim3(12, 25), 512, GEMM_SMEM>>>(ap, Wo, bo, outp, QTOT, DIM, DIM, nullptr);
}

// round 6
// speedup vs baseline: 1.1840x; 1.1840x over previous
#include <cuda_runtime.h>
#include <cuda_fp16.h>

#define HW    1560
#define TQ    2
#define QTOT  3120
#define KTOT  12480
#define HEADS 12
#define DH    128
#define DIM   1536

// ---------------- scratch (device globals; no allocation allowed) ----------------
__device__ float g_q[QTOT * DIM];
__device__ float g_k[KTOT * DIM];
__device__ float g_v[KTOT * DIM];
__device__ float g_attn[QTOT * DIM];

// ---------------- helpers ----------------
__device__ __forceinline__ unsigned f2tf(float f) {
    unsigned u;
    asm("cvt.rna.tf32.f32 %0, %1;" : "=r"(u) : "f"(f));
    return u;
}

// fp16 mma: D(4xf32) += A(4xf16x2) * B(2xf16x2)   [m16n8k16]
__device__ __forceinline__ void mma_f16(float* d, const unsigned* a, unsigned b0, unsigned b1) {
    asm volatile(
        "mma.sync.aligned.m16n8k16.row.col.f32.f16.f16.f32 "
        "{%0,%1,%2,%3}, {%4,%5,%6,%7}, {%8,%9}, {%0,%1,%2,%3};"
        : "+f"(d[0]), "+f"(d[1]), "+f"(d[2]), "+f"(d[3])
        : "r"(a[0]), "r"(a[1]), "r"(a[2]), "r"(a[3]), "r"(b0), "r"(b1));
}

// tf32 mma: D(4xf32) += A(4xtf32) * B(2xtf32)   [m16n8k8]
__device__ __forceinline__ void mma_tf32(float* d, const unsigned* a, unsigned b0, unsigned b1) {
    asm volatile(
        "mma.sync.aligned.m16n8k8.row.col.f32.tf32.tf32.f32 "
        "{%0,%1,%2,%3}, {%4,%5,%6,%7}, {%8,%9}, {%0,%1,%2,%3};"
        : "+f"(d[0]), "+f"(d[1]), "+f"(d[2]), "+f"(d[3])
        : "r"(a[0]), "r"(a[1]), "r"(a[2]), "r"(a[3]), "r"(b0), "r"(b1));
}

__device__ __forceinline__ uint2 f4_to_h4(float4 v) {
    __half2 h0 = __float22half2_rn(make_float2(v.x, v.y));
    __half2 h1 = __float22half2_rn(make_float2(v.z, v.w));
    uint2 r;
    r.x = *(unsigned*)&h0;
    r.y = *(unsigned*)&h1;
    return r;
}

__device__ __forceinline__ bool block_needed(int b, const int* __restrict__ sel) {
    return (sel[0] == b) | (sel[1] == b) | (sel[2] == b) | (sel[3] == b);
}

// ---------------- GEMM: C[M,N] = A[M,K] @ W[N,K]^T + bias[N]  (fp16 mma, fp32 accum) ----------
// block tile 128x128x32, 256 threads = 8 warps (2M x 4N), warp tile 64x32.
// fp16 operands in smem (half LDS traffic vs tf32), k16 mma (2x MACs/instr).
// Ping-pong double-buffered smem, one __syncthreads per k-tile.
#define GEMM_STAGE_H (128 * 40)                   // halves per matrix per stage (pad 32->40)
#define GEMM_SMEM    (2 * 2 * GEMM_STAGE_H * 2)   // 2 stages x (A+W) x 2B = 40960 bytes

__global__ __launch_bounds__(256, 1) void gemm_bias_f16(
    const float* __restrict__ A, const float* __restrict__ W,
    const float* __restrict__ bias, float* __restrict__ C,
    int M, int N, int K, const int* __restrict__ sel)
{
    extern __shared__ __half gh[];
    const int bm = blockIdx.y * 128, bn = blockIdx.x * 128;

    if (sel) {
        int b0 = bm / HW;
        int b1 = (bm + 127) / HW;
        if (!block_needed(b0, sel) && !block_needed(b1, sel)) return;
    }

    const int tid  = threadIdx.x;
    const int warp = tid >> 5, lane = tid & 31;
    const int g = lane >> 2, t4 = lane & 3;
    const int wm = warp >> 2, wn = warp & 3;

    float acc[4][4][4] = {};

    const int lc = (tid & 7) * 4;  // col within 32-wide k tile (float4 granule)
    const int lr = tid >> 3;       // base row (0..31), rows lr + 32*i

    float4 aF[4], wF[4];
    #pragma unroll
    for (int i = 0; i < 4; i++) {
        int row = lr + 32 * i;
        long ar = bm + row;
        aF[i] = (ar < M) ? *(const float4*)(A + ar * (long)K + lc)
                         : make_float4(0.f, 0.f, 0.f, 0.f);
        wF[i] = *(const float4*)(W + (long)(bn + row) * K + lc);
    }

    // prime stage 0
    {
        __half* As = gh;
        __half* Ws = gh + GEMM_STAGE_H;
        #pragma unroll
        for (int i = 0; i < 4; i++) {
            int row = lr + 32 * i;
            *(uint2*)&As[row * 40 + lc] = f4_to_h4(aF[i]);
            *(uint2*)&Ws[row * 40 + lc] = f4_to_h4(wF[i]);
        }
    }
    __syncthreads();

    const int KT = K >> 5;
    for (int kt = 0; kt < KT; kt++) {
        const __half* As = gh + (kt & 1) * 2 * GEMM_STAGE_H;
        const __half* Ws = As + GEMM_STAGE_H;

        // issue global loads for next tile (latency hidden under compute)
        if (kt + 1 < KT) {
            int k0 = (kt + 1) << 5;
            #pragma unroll
            for (int i = 0; i < 4; i++) {
                int row = lr + 32 * i;
                long ar = bm + row;
                aF[i] = (ar < M) ? *(const float4*)(A + ar * (long)K + k0 + lc)
                                 : make_float4(0.f, 0.f, 0.f, 0.f);
                wF[i] = *(const float4*)(W + (long)(bn + row) * K + k0 + lc);
            }
        }

        #pragma unroll
        for (int kk = 0; kk < 2; kk++) {          // two k16 steps per 32-k tile
            const int kb = kk * 16;
            unsigned a[4][4], b[4][2];
            #pragma unroll
            for (int mt = 0; mt < 4; mt++) {
                int m = wm * 64 + mt * 16 + g;
                a[mt][0] = *(const unsigned*)&As[m * 40 + kb + 2 * t4];
                a[mt][1] = *(const unsigned*)&As[(m + 8) * 40 + kb + 2 * t4];
                a[mt][2] = *(const unsigned*)&As[m * 40 + kb + 8 + 2 * t4];
                a[mt][3] = *(const unsigned*)&As[(m + 8) * 40 + kb + 8 + 2 * t4];
            }
            #pragma unroll
            for (int nt = 0; nt < 4; nt++) {
                int n = wn * 32 + nt * 8 + g;
                b[nt][0] = *(const unsigned*)&Ws[n * 40 + kb + 2 * t4];
                b[nt][1] = *(const unsigned*)&Ws[n * 40 + kb + 8 + 2 * t4];
            }
            #pragma unroll
            for (int nt = 0; nt < 4; nt++) {
                #pragma unroll
                for (int mt = 0; mt < 4; mt++)
                    mma_f16(acc[mt][nt], a[mt], b[nt][0], b[nt][1]);
            }
        }

        // store next tile into the other stage
        if (kt + 1 < KT) {
            __half* Asn = gh + ((kt + 1) & 1) * 2 * GEMM_STAGE_H;
            __half* Wsn = Asn + GEMM_STAGE_H;
            #pragma unroll
            for (int i = 0; i < 4; i++) {
                int row = lr + 32 * i;
                *(uint2*)&Asn[row * 40 + lc] = f4_to_h4(aF[i]);
                *(uint2*)&Wsn[row * 40 + lc] = f4_to_h4(wF[i]);
            }
        }
        __syncthreads();
    }

    #pragma unroll
    for (int mt = 0; mt < 4; mt++) {
        int r = bm + wm * 64 + mt * 16 + g;
        #pragma unroll
        for (int nt = 0; nt < 4; nt++) {
            int c = bn + wn * 32 + nt * 8 + t4 * 2;
            float b0 = bias[c], b1 = bias[c + 1];
            if (r < M)
                *(float2*)(C + (long)r * N + c) =
                    make_float2(acc[mt][nt][0] + b0, acc[mt][nt][1] + b1);
            if (r + 8 < M)
                *(float2*)(C + (long)(r + 8) * N + c) =
                    make_float2(acc[mt][nt][2] + b0, acc[mt][nt][3] + b1);
        }
    }
}

// ---------------- fused RMSNorm + RoPE (in-place, one row per CTA) ----------------
__global__ __launch_bounds__(384) void rmsnorm_rope_kernel(
    float* __restrict__ x, const float* __restrict__ gamma,
    const float* __restrict__ fc, const float* __restrict__ fs,
    const int* __restrict__ sel)
{
    __shared__ float red[12];
    __shared__ float rinv_s;
    const int row = blockIdx.x, tid = threadIdx.x;

    if (sel && !block_needed(row / HW, sel)) return;

    float4 v = *(float4*)(x + (long)row * DIM + tid * 4);
    float ss = v.x * v.x + v.y * v.y + v.z * v.z + v.w * v.w;
    #pragma unroll
    for (int s = 16; s > 0; s >>= 1) ss += __shfl_xor_sync(0xffffffffu, ss, s);
    if ((tid & 31) == 0) red[tid >> 5] = ss;
    __syncthreads();
    if (tid < 32) {
        float t = (tid < 12) ? red[tid] : 0.f;
        #pragma unroll
        for (int s = 16; s > 0; s >>= 1) t += __shfl_xor_sync(0xffffffffu, t, s);
        if (tid == 0) rinv_s = rsqrtf(t * (1.0f / DIM) + 1e-5f);
    }
    __syncthreads();
    float r = rinv_s;

    float4 g4 = *(const float4*)(gamma + tid * 4);
    float x0 = v.x * r * g4.x, x1 = v.y * r * g4.y;
    float x2 = v.z * r * g4.z, x3 = v.w * r * g4.w;

    int hd = (tid * 4) & (DH - 1);
    float4 c4 = *(const float4*)(fc + (long)row * DH + hd);
    float4 s4 = *(const float4*)(fs + (long)row * DH + hd);
    float4 o;
    o.x = x0 * c4.x - x1 * s4.y;
    o.y = x0 * s4.y + x1 * c4.x;
    o.z = x2 * c4.z - x3 * s4.w;
    o.w = x2 * s4.w + x3 * c4.z;
    *(float4*)(x + (long)row * DIM + tid * 4) = o;
}

// ---------------- fused block-sparse attention ----------------
// grid (13 qblocks, TQ, HEADS), 256 threads = 8 warps (4 M x 2 N)
// QK^T in fp16 (k16 mma, halved instr count + LDS); softmax fp32; P@V in tf32.
// smem byte offsets:
#define AQ_OFF  0                        // half  [128][136]  34816 B
#define AK_OFF  34816                    // half  [64][136]   17408 B
#define AV_OFF  52224                    // uint  [64][136]   34816 B (tf32)
#define AP_OFF  87040                    // uint  [128][68]   34816 B (tf32)
#define ARS_OFF 121856                   // float [128][2]    1024 B
#define ATT_SMEM 122880

__global__ __launch_bounds__(256) void attention_kernel(
    const float* __restrict__ q, const float* __restrict__ k,
    const float* __restrict__ v, const int* __restrict__ sel,
    float* __restrict__ out)
{
    extern __shared__ char asm_[];
    __half*   Qh = (__half*)(asm_ + AQ_OFF);   // [128][136]
    __half*   Kh = (__half*)(asm_ + AK_OFF);   // [64][136]
    unsigned* Vs = (unsigned*)(asm_ + AV_OFF); // [64][136]
    unsigned* Ps = (unsigned*)(asm_ + AP_OFF); // [128][68]
    float*    RS = (float*)(asm_ + ARS_OFF);   // [128][2]

    const int qb = blockIdx.x, t = blockIdx.y, h = blockIdx.z;
    const int tid = threadIdx.x, warp = tid >> 5, lane = tid & 31;
    const int g = lane >> 2, t4 = lane & 3;
    const int wm = warp >> 1, wn = warp & 1;

    // load Q tile (fp16, zero-fill tail rows)
    const float* qbase = q + (long)(t * HW) * DIM + (long)h * DH;
    {
        const int c4 = (tid & 31) * 4;
        const int lr0 = tid >> 5;
        #pragma unroll
        for (int i = 0; i < 16; i++) {
            int r = lr0 + i * 8;
            int qr = qb * 128 + r;
            float4 val = (qr < HW) ? *(const float4*)(qbase + (long)qr * DIM + c4)
                                   : make_float4(0.f, 0.f, 0.f, 0.f);
            *(uint2*)&Qh[r * 136 + c4] = f4_to_h4(val);
        }
    }

    float oacc[2][8][4] = {};
    float rpart[2][2] = {};

    int s0 = sel[t * 2 + 0]; if (s0 < 0) s0 = 0;
    int s1 = sel[t * 2 + 1];
    int nb = (s1 >= 0) ? 2 : 1;

    __syncthreads();

    const float SC   = 0.08838834764831843f * 1.4426950408889634f;
    const float OFFL = 12.0f * 1.4426950408889634f;

    for (int bi = 0; bi < nb; bi++) {
        int blk = (bi == 0) ? s0 : s1;
        const float* kbp = k + (long)blk * HW * DIM + (long)h * DH;
        const float* vbp = v + (long)blk * HW * DIM + (long)h * DH;

        for (int n0 = 0; n0 < HW; n0 += 64) {
            // load K (fp16) and V (tf32) tiles
            {
                const int c4 = (tid & 31) * 4;
                const int lr0 = tid >> 5;
                #pragma unroll
                for (int i = 0; i < 8; i++) {
                    int r = lr0 + i * 8;
                    int kr = n0 + r;
                    float4 kv, vv;
                    if (kr < HW) {
                        kv = *(const float4*)(kbp + (long)kr * DIM + c4);
                        vv = *(const float4*)(vbp + (long)kr * DIM + c4);
                    } else {
                        kv = make_float4(0.f, 0.f, 0.f, 0.f);
                        vv = kv;
                    }
                    *(uint2*)&Kh[r * 136 + c4] = f4_to_h4(kv);
                    *(uint4*)&Vs[r * 136 + c4] =
                        make_uint4(f2tf(vv.x), f2tf(vv.y), f2tf(vv.z), f2tf(vv.w));
                }
            }
            __syncthreads();

            // QK^T : S[128][64], fp16 k16 mma, warp tile 32 rows x 32 keys
            float sacc[2][4][4] = {};
            #pragma unroll
            for (int ks = 0; ks < 8; ks++) {
                const int kb = ks * 16;
                unsigned a[2][4], b[4][2];
                #pragma unroll
                for (int mt = 0; mt < 2; mt++) {
                    int m = wm * 32 + mt * 16 + g;
                    a[mt][0] = *(const unsigned*)&Qh[m * 136 + kb + 2 * t4];
                    a[mt][1] = *(const unsigned*)&Qh[(m + 8) * 136 + kb + 2 * t4];
                    a[mt][2] = *(const unsigned*)&Qh[m * 136 + kb + 8 + 2 * t4];
                    a[mt][3] = *(const unsigned*)&Qh[(m + 8) * 136 + kb + 8 + 2 * t4];
                }
                #pragma unroll
                for (int nt = 0; nt < 4; nt++) {
                    int n = wn * 32 + nt * 8 + g;
                    b[nt][0] = *(const unsigned*)&Kh[n * 136 + kb + 2 * t4];
                    b[nt][1] = *(const unsigned*)&Kh[n * 136 + kb + 8 + 2 * t4];
                }
                #pragma unroll
                for (int nt = 0; nt < 4; nt++) {
                    mma_f16(sacc[0][nt], a[0], b[nt][0], b[nt][1]);
                    mma_f16(sacc[1][nt], a[1], b[nt][0], b[nt][1]);
                }
            }

            // exp (fixed offset), zero invalid columns exactly, stash P (tf32)
            #pragma unroll
            for (int mt = 0; mt < 2; mt++) {
                int rg = wm * 32 + mt * 16 + g;
                #pragma unroll
                for (int nt = 0; nt < 4; nt++) {
                    int cn = wn * 32 + nt * 8 + 2 * t4;
                    bool v0 = (n0 + cn) < HW, v1 = (n0 + cn + 1) < HW;
                    float p0 = v0 ? exp2f(fmaf(sacc[mt][nt][0], SC, -OFFL)) : 0.f;
                    float p1 = v1 ? exp2f(fmaf(sacc[mt][nt][1], SC, -OFFL)) : 0.f;
                    float p2 = v0 ? exp2f(fmaf(sacc[mt][nt][2], SC, -OFFL)) : 0.f;
                    float p3 = v1 ? exp2f(fmaf(sacc[mt][nt][3], SC, -OFFL)) : 0.f;
                    rpart[mt][0] += p0 + p1;
                    rpart[mt][1] += p2 + p3;
                    *(uint2*)&Ps[rg * 68 + cn]       = make_uint2(f2tf(p0), f2tf(p1));
                    *(uint2*)&Ps[(rg + 8) * 68 + cn] = make_uint2(f2tf(p2), f2tf(p3));
                }
            }
            // only the 2 warps sharing this wm row-group exchange P columns
            asm volatile("bar.sync %0, %1;" :: "r"(wm + 1), "r"(64) : "memory");

            // P @ V : out += P[128][64] * V[64][128]  (tf32 k8 mma)
            #pragma unroll
            for (int ks = 0; ks < 8; ks++) {
                const int kb = ks * 8;
                unsigned a[2][4];
                #pragma unroll
                for (int mt = 0; mt < 2; mt++) {
                    int m = wm * 32 + mt * 16 + g;
                    a[mt][0] = Ps[m * 68 + kb + t4];
                    a[mt][1] = Ps[(m + 8) * 68 + kb + t4];
                    a[mt][2] = Ps[m * 68 + kb + t4 + 4];
                    a[mt][3] = Ps[(m + 8) * 68 + kb + t4 + 4];
                }
                #pragma unroll
                for (int nt = 0; nt < 8; nt++) {
                    int d = wn * 64 + nt * 8 + g;
                    unsigned b0 = Vs[(kb + t4) * 136 + d];
                    unsigned b1 = Vs[(kb + t4 + 4) * 136 + d];
                    mma_tf32(oacc[0][nt], a[0], b0, b1);
                    mma_tf32(oacc[1][nt], a[1], b0, b1);
                }
            }
            __syncthreads();
        }
    }

    // row-sum reduce: quad shuffle, then cross-warp via smem
    #pragma unroll
    for (int mt = 0; mt < 2; mt++) {
        #pragma unroll
        for (int hh = 0; hh < 2; hh++) {
            float s = rpart[mt][hh];
            s += __shfl_xor_sync(0xffffffffu, s, 1);
            s += __shfl_xor_sync(0xffffffffu, s, 2);
            if (t4 == 0) RS[(wm * 32 + mt * 16 + hh * 8 + g) * 2 + wn] = s;
        }
    }
    __syncthreads();

    float* obase = out + (long)(t * HW) * DIM + h * DH;
    #pragma unroll
    for (int mt = 0; mt < 2; mt++) {
        int r = wm * 32 + mt * 16 + g;
        float inv0 = 1.f / (RS[r * 2] + RS[r * 2 + 1]);
        float inv1 = 1.f / (RS[(r + 8) * 2] + RS[(r + 8) * 2 + 1]);
        int qr0 = qb * 128 + r, qr1 = qr0 + 8;
        #pragma unroll
        for (int nt = 0; nt < 8; nt++) {
            int d = wn * 64 + nt * 8 + 2 * t4;
            if (qr0 < HW)
                *(float2*)(obase + (long)qr0 * DIM + d) =
                    make_float2(oacc[mt][nt][0] * inv0, oacc[mt][nt][1] * inv0);
            if (qr1 < HW)
                *(float2*)(obase + (long)qr1 * DIM + d) =
                    make_float2(oacc[mt][nt][2] * inv1, oacc[mt][nt][3] * inv1);
        }
    }
}

// ---------------- launch ----------------
extern "C" void kernel_launch(void* const* d_in, const int* in_sizes, int n_in,
                              void* d_out, int out_size)
{
    const float* hidden  = (const float*)d_in[0];
    const float* history = (const float*)d_in[1];
    const float* fc   = (const float*)d_in[2];
    const float* fs   = (const float*)d_in[3];
    const float* fch  = (const float*)d_in[4];
    const float* fsh  = (const float*)d_in[5];
    const int*   sel  = (const int*)d_in[6];
    const float* Wq = (const float*)d_in[7];
    const float* bq = (const float*)d_in[8];
    const float* Wk = (const float*)d_in[9];
    const float* bk = (const float*)d_in[10];
    const float* Wv = (const float*)d_in[11];
    const float* bv = (const float*)d_in[12];
    const float* Wo = (const float*)d_in[13];
    const float* bo = (const float*)d_in[14];
    const float* gq = (const float*)d_in[15];
    const float* gk = (const float*)d_in[16];
    float* outp = (float*)d_out;

    float *qp, *kp, *vp, *ap;
    cudaGetSymbolAddress((void**)&qp, g_q);
    cudaGetSymbolAddress((void**)&kp, g_k);
    cudaGetSymbolAddress((void**)&vp, g_v);
    cudaGetSymbolAddress((void**)&ap, g_attn);

    cudaFuncSetAttribute(gemm_bias_f16,
                         cudaFuncAttributeMaxDynamicSharedMemorySize, GEMM_SMEM);
    cudaFuncSetAttribute(attention_kernel,
                         cudaFuncAttributeMaxDynamicSharedMemorySize, ATT_SMEM);

    gemm_bias_f16<<<dim3(12, 25), 256, GEMM_SMEM>>>(hidden,  Wq, bq, qp, QTOT, DIM, DIM, nullptr);
    gemm_bias_f16<<<dim3(12, 98), 256, GEMM_SMEM>>>(history, Wk, bk, kp, KTOT, DIM, DIM, sel);
    gemm_bias_f16<<<dim3(12, 98), 256, GEMM_SMEM>>>(history, Wv, bv, vp, KTOT, DIM, DIM, sel);
    rmsnorm_rope_kernel<<<QTOT, 384>>>(qp, gq, fc, fs, nullptr);
    rmsnorm_rope_kernel<<<KTOT, 384>>>(kp, gk, fch, fsh, sel);
    attention_kernel<<<dim3(13, TQ, HEADS), 256, ATT_SMEM>>>(qp, kp, vp, sel, ap);
    gemm_bias_f16<<<dim3(12, 25), 256, GEMM_SMEM>>>(ap, Wo, bo, outp, QTOT, DIM, DIM, nullptr);
}

// round 7
// speedup vs baseline: 1.4177x; 1.1974x over previous
#include <cuda_runtime.h>
#include <cuda_fp16.h>

#define HW    1560
#define TQ    2
#define QTOT  3120
#define KTOT  12480
#define HEADS 12
#define DH    128
#define DIM   1536

// ---------------- scratch (device globals; no allocation allowed) ----------------
__device__ float g_q[QTOT * DIM];
__device__ float g_k[KTOT * DIM];
__device__ float g_v[KTOT * DIM];
__device__ float g_attn[QTOT * DIM];

// ---------------- helpers ----------------
// fp16 mma: D(4xf32) += A(4xf16x2) * B(2xf16x2)   [m16n8k16]
__device__ __forceinline__ void mma_f16(float* d, const unsigned* a, unsigned b0, unsigned b1) {
    asm volatile(
        "mma.sync.aligned.m16n8k16.row.col.f32.f16.f16.f32 "
        "{%0,%1,%2,%3}, {%4,%5,%6,%7}, {%8,%9}, {%0,%1,%2,%3};"
        : "+f"(d[0]), "+f"(d[1]), "+f"(d[2]), "+f"(d[3])
        : "r"(a[0]), "r"(a[1]), "r"(a[2]), "r"(a[3]), "r"(b0), "r"(b1));
}

__device__ __forceinline__ uint2 f4_to_h4(float4 v) {
    __half2 h0 = __float22half2_rn(make_float2(v.x, v.y));
    __half2 h1 = __float22half2_rn(make_float2(v.z, v.w));
    uint2 r;
    r.x = *(unsigned*)&h0;
    r.y = *(unsigned*)&h1;
    return r;
}

__device__ __forceinline__ bool block_needed(int b, const int* __restrict__ sel) {
    return (sel[0] == b) | (sel[1] == b) | (sel[2] == b) | (sel[3] == b);
}

// ---------------- GEMM: C[M,N] = A[M,K] @ W[N,K]^T + bias[N]  (fp16 mma, fp32 accum) ----------
// block tile 128x128x32, 256 threads = 8 warps (2M x 4N), warp tile 64x32.
// Ping-pong double-buffered smem, one __syncthreads per k-tile. (unchanged from R6)
#define GEMM_STAGE_H (128 * 40)
#define GEMM_SMEM    (2 * 2 * GEMM_STAGE_H * 2)   // 40960 bytes

__global__ __launch_bounds__(256, 1) void gemm_bias_f16(
    const float* __restrict__ A, const float* __restrict__ W,
    const float* __restrict__ bias, float* __restrict__ C,
    int M, int N, int K, const int* __restrict__ sel)
{
    extern __shared__ __half gh[];
    const int bm = blockIdx.y * 128, bn = blockIdx.x * 128;

    if (sel) {
        int b0 = bm / HW;
        int b1 = (bm + 127) / HW;
        if (!block_needed(b0, sel) && !block_needed(b1, sel)) return;
    }

    const int tid  = threadIdx.x;
    const int warp = tid >> 5, lane = tid & 31;
    const int g = lane >> 2, t4 = lane & 3;
    const int wm = warp >> 2, wn = warp & 3;

    float acc[4][4][4] = {};

    const int lc = (tid & 7) * 4;
    const int lr = tid >> 3;

    float4 aF[4], wF[4];
    #pragma unroll
    for (int i = 0; i < 4; i++) {
        int row = lr + 32 * i;
        long ar = bm + row;
        aF[i] = (ar < M) ? *(const float4*)(A + ar * (long)K + lc)
                         : make_float4(0.f, 0.f, 0.f, 0.f);
        wF[i] = *(const float4*)(W + (long)(bn + row) * K + lc);
    }

    {
        __half* As = gh;
        __half* Ws = gh + GEMM_STAGE_H;
        #pragma unroll
        for (int i = 0; i < 4; i++) {
            int row = lr + 32 * i;
            *(uint2*)&As[row * 40 + lc] = f4_to_h4(aF[i]);
            *(uint2*)&Ws[row * 40 + lc] = f4_to_h4(wF[i]);
        }
    }
    __syncthreads();

    const int KT = K >> 5;
    for (int kt = 0; kt < KT; kt++) {
        const __half* As = gh + (kt & 1) * 2 * GEMM_STAGE_H;
        const __half* Ws = As + GEMM_STAGE_H;

        if (kt + 1 < KT) {
            int k0 = (kt + 1) << 5;
            #pragma unroll
            for (int i = 0; i < 4; i++) {
                int row = lr + 32 * i;
                long ar = bm + row;
                aF[i] = (ar < M) ? *(const float4*)(A + ar * (long)K + k0 + lc)
                                 : make_float4(0.f, 0.f, 0.f, 0.f);
                wF[i] = *(const float4*)(W + (long)(bn + row) * K + k0 + lc);
            }
        }

        #pragma unroll
        for (int kk = 0; kk < 2; kk++) {
            const int kb = kk * 16;
            unsigned a[4][4], b[4][2];
            #pragma unroll
            for (int mt = 0; mt < 4; mt++) {
                int m = wm * 64 + mt * 16 + g;
                a[mt][0] = *(const unsigned*)&As[m * 40 + kb + 2 * t4];
                a[mt][1] = *(const unsigned*)&As[(m + 8) * 40 + kb + 2 * t4];
                a[mt][2] = *(const unsigned*)&As[m * 40 + kb + 8 + 2 * t4];
                a[mt][3] = *(const unsigned*)&As[(m + 8) * 40 + kb + 8 + 2 * t4];
            }
            #pragma unroll
            for (int nt = 0; nt < 4; nt++) {
                int n = wn * 32 + nt * 8 + g;
                b[nt][0] = *(const unsigned*)&Ws[n * 40 + kb + 2 * t4];
                b[nt][1] = *(const unsigned*)&Ws[n * 40 + kb + 8 + 2 * t4];
            }
            #pragma unroll
            for (int nt = 0; nt < 4; nt++) {
                #pragma unroll
                for (int mt = 0; mt < 4; mt++)
                    mma_f16(acc[mt][nt], a[mt], b[nt][0], b[nt][1]);
            }
        }

        if (kt + 1 < KT) {
            __half* Asn = gh + ((kt + 1) & 1) * 2 * GEMM_STAGE_H;
            __half* Wsn = Asn + GEMM_STAGE_H;
            #pragma unroll
            for (int i = 0; i < 4; i++) {
                int row = lr + 32 * i;
                *(uint2*)&Asn[row * 40 + lc] = f4_to_h4(aF[i]);
                *(uint2*)&Wsn[row * 40 + lc] = f4_to_h4(wF[i]);
            }
        }
        __syncthreads();
    }

    #pragma unroll
    for (int mt = 0; mt < 4; mt++) {
        int r = bm + wm * 64 + mt * 16 + g;
        #pragma unroll
        for (int nt = 0; nt < 4; nt++) {
            int c = bn + wn * 32 + nt * 8 + t4 * 2;
            float b0 = bias[c], b1 = bias[c + 1];
            if (r < M)
                *(float2*)(C + (long)r * N + c) =
                    make_float2(acc[mt][nt][0] + b0, acc[mt][nt][1] + b1);
            if (r + 8 < M)
                *(float2*)(C + (long)(r + 8) * N + c) =
                    make_float2(acc[mt][nt][2] + b0, acc[mt][nt][3] + b1);
        }
    }
}

// ---------------- fused RMSNorm + RoPE (in-place, one row per CTA) ----------------
__global__ __launch_bounds__(384) void rmsnorm_rope_kernel(
    float* __restrict__ x, const float* __restrict__ gamma,
    const float* __restrict__ fc, const float* __restrict__ fs,
    const int* __restrict__ sel)
{
    __shared__ float red[12];
    __shared__ float rinv_s;
    const int row = blockIdx.x, tid = threadIdx.x;

    if (sel && !block_needed(row / HW, sel)) return;

    float4 v = *(float4*)(x + (long)row * DIM + tid * 4);
    float ss = v.x * v.x + v.y * v.y + v.z * v.z + v.w * v.w;
    #pragma unroll
    for (int s = 16; s > 0; s >>= 1) ss += __shfl_xor_sync(0xffffffffu, ss, s);
    if ((tid & 31) == 0) red[tid >> 5] = ss;
    __syncthreads();
    if (tid < 32) {
        float t = (tid < 12) ? red[tid] : 0.f;
        #pragma unroll
        for (int s = 16; s > 0; s >>= 1) t += __shfl_xor_sync(0xffffffffu, t, s);
        if (tid == 0) rinv_s = rsqrtf(t * (1.0f / DIM) + 1e-5f);
    }
    __syncthreads();
    float r = rinv_s;

    float4 g4 = *(const float4*)(gamma + tid * 4);
    float x0 = v.x * r * g4.x, x1 = v.y * r * g4.y;
    float x2 = v.z * r * g4.z, x3 = v.w * r * g4.w;

    int hd = (tid * 4) & (DH - 1);
    float4 c4 = *(const float4*)(fc + (long)row * DH + hd);
    float4 s4 = *(const float4*)(fs + (long)row * DH + hd);
    float4 o;
    o.x = x0 * c4.x - x1 * s4.y;
    o.y = x0 * s4.y + x1 * c4.x;
    o.z = x2 * c4.z - x3 * s4.w;
    o.w = x2 * s4.w + x3 * c4.z;
    *(float4*)(x + (long)row * DIM + tid * 4) = o;
}

// ---------------- fused block-sparse attention (register-P, all-fp16 mma) ----------------
// grid (13 qblocks, TQ, HEADS), 256 threads = 8 warps; warp w owns q-rows w*16..+16.
// QK fp16 -> exp in regs -> P fragments ARE the fp16 PV A-fragments (no P smem, no barrier).
// V stored key-pair-interleaved half2 so PV B-frags are single 4B LDS.
// Row sums complete within each warp (quad shuffles). 68KB smem -> 2 CTA/SM.
#define AQ_OFF  0                        // half  [128][136]  34816 B
#define AK_OFF  34816                    // half  [64][136]   17408 B
#define AV_OFF  52224                    // uint  [32 pairs][136]  17408 B (half2: even,odd key)
#define ATT_SMEM 69632

__global__ __launch_bounds__(256, 2) void attention_kernel(
    const float* __restrict__ q, const float* __restrict__ k,
    const float* __restrict__ v, const int* __restrict__ sel,
    float* __restrict__ out)
{
    extern __shared__ char asm_[];
    __half*   Qh = (__half*)(asm_ + AQ_OFF);   // [128][136]
    __half*   Kh = (__half*)(asm_ + AK_OFF);   // [64][136]
    unsigned* Vp = (unsigned*)(asm_ + AV_OFF); // [32][136] half2(V[2p][d], V[2p+1][d])

    const int qb = blockIdx.x, t = blockIdx.y, h = blockIdx.z;
    const int tid = threadIdx.x, warp = tid >> 5, lane = tid & 31;
    const int g = lane >> 2, t4 = lane & 3;

    // load Q tile (fp16, zero-fill tail rows)
    const float* qbase = q + (long)(t * HW) * DIM + (long)h * DH;
    {
        const int c4 = (tid & 31) * 4;
        const int lr0 = tid >> 5;
        #pragma unroll
        for (int i = 0; i < 16; i++) {
            int r = lr0 + i * 8;
            int qr = qb * 128 + r;
            float4 val = (qr < HW) ? *(const float4*)(qbase + (long)qr * DIM + c4)
                                   : make_float4(0.f, 0.f, 0.f, 0.f);
            *(uint2*)&Qh[r * 136 + c4] = f4_to_h4(val);
        }
    }

    float oacc[16][4] = {};      // rows (g, g+8) x d = nt*8 + 2t4(+1)
    float rp0 = 0.f, rp1 = 0.f;  // row sums for rows g / g+8

    int s0 = sel[t * 2 + 0]; if (s0 < 0) s0 = 0;
    int s1 = sel[t * 2 + 1];
    int nb = (s1 >= 0) ? 2 : 1;

    __syncthreads();

    const float SC   = 0.08838834764831843f * 1.4426950408889634f;  // (1/sqrt(DH))*log2(e)
    const float OFFL = 4.0f * 1.4426950408889634f;                   // keep fp16 P normal-range

    for (int bi = 0; bi < nb; bi++) {
        int blk = (bi == 0) ? s0 : s1;
        const float* kbp = k + (long)blk * HW * DIM + (long)h * DH;
        const float* vbp = v + (long)blk * HW * DIM + (long)h * DH;

        for (int n0 = 0; n0 < HW; n0 += 64) {
            // ---- load K tile (fp16) ----
            {
                const int c4 = (tid & 31) * 4;
                const int lr0 = tid >> 5;
                #pragma unroll
                for (int i = 0; i < 8; i++) {
                    int r = lr0 + i * 8;
                    int kr = n0 + r;
                    float4 kv = (kr < HW) ? *(const float4*)(kbp + (long)kr * DIM + c4)
                                          : make_float4(0.f, 0.f, 0.f, 0.f);
                    *(uint2*)&Kh[r * 136 + c4] = f4_to_h4(kv);
                }
            }
            // ---- load V tile, key-pair interleaved ----
            #pragma unroll
            for (int i = 0; i < 4; i++) {
                int idx = i * 256 + tid;
                int p = idx >> 5;            // pair 0..31
                int d = (idx & 31) * 4;
                int kr0 = n0 + 2 * p;
                float4 v0 = (kr0 < HW)     ? *(const float4*)(vbp + (long)kr0 * DIM + d)
                                           : make_float4(0.f, 0.f, 0.f, 0.f);
                float4 v1 = (kr0 + 1 < HW) ? *(const float4*)(vbp + (long)(kr0 + 1) * DIM + d)
                                           : make_float4(0.f, 0.f, 0.f, 0.f);
                __half2 h0 = __floats2half2_rn(v0.x, v1.x);
                __half2 h1 = __floats2half2_rn(v0.y, v1.y);
                __half2 h2 = __floats2half2_rn(v0.z, v1.z);
                __half2 h3 = __floats2half2_rn(v0.w, v1.w);
                uint2 u01 = make_uint2(*(unsigned*)&h0, *(unsigned*)&h1);
                uint2 u23 = make_uint2(*(unsigned*)&h2, *(unsigned*)&h3);
                *(uint2*)&Vp[p * 136 + d]     = u01;
                *(uint2*)&Vp[p * 136 + d + 2] = u23;
            }
            __syncthreads();

            // ---- QK^T: rows warp*16..+16 x 64 keys ----
            float sacc[8][4] = {};
            #pragma unroll
            for (int ks = 0; ks < 8; ks++) {
                const int kb = ks * 16;
                unsigned a[4];
                int m = warp * 16 + g;
                a[0] = *(const unsigned*)&Qh[m * 136 + kb + 2 * t4];
                a[1] = *(const unsigned*)&Qh[(m + 8) * 136 + kb + 2 * t4];
                a[2] = *(const unsigned*)&Qh[m * 136 + kb + 8 + 2 * t4];
                a[3] = *(const unsigned*)&Qh[(m + 8) * 136 + kb + 8 + 2 * t4];
                #pragma unroll
                for (int nt = 0; nt < 8; nt++) {
                    int n = nt * 8 + g;
                    unsigned b0 = *(const unsigned*)&Kh[n * 136 + kb + 2 * t4];
                    unsigned b1 = *(const unsigned*)&Kh[n * 136 + kb + 8 + 2 * t4];
                    mma_f16(sacc[nt], a, b0, b1);
                }
            }

            // ---- softmax numerators in regs; P fragments = PV A-fragments ----
            unsigned ap[4][4];
            #pragma unroll
            for (int nt = 0; nt < 8; nt++) {
                int cn = nt * 8 + 2 * t4;
                bool m0 = (n0 + cn) < HW, m1 = (n0 + cn + 1) < HW;
                float p0 = m0 ? exp2f(fmaf(sacc[nt][0], SC, -OFFL)) : 0.f;
                float p1 = m1 ? exp2f(fmaf(sacc[nt][1], SC, -OFFL)) : 0.f;
                float p2 = m0 ? exp2f(fmaf(sacc[nt][2], SC, -OFFL)) : 0.f;
                float p3 = m1 ? exp2f(fmaf(sacc[nt][3], SC, -OFFL)) : 0.f;
                rp0 += p0 + p1;
                rp1 += p2 + p3;
                __half2 h01 = __floats2half2_rn(p0, p1);
                __half2 h23 = __floats2half2_rn(p2, p3);
                ap[nt >> 1][(nt & 1) * 2 + 0] = *(unsigned*)&h01;
                ap[nt >> 1][(nt & 1) * 2 + 1] = *(unsigned*)&h23;
            }

            // ---- P @ V: oacc[rows (g,g+8)][d 0..127] over these 64 keys ----
            #pragma unroll
            for (int kp = 0; kp < 4; kp++) {
                #pragma unroll
                for (int nt = 0; nt < 16; nt++) {
                    unsigned b0 = Vp[(kp * 8 + t4) * 136 + nt * 8 + g];
                    unsigned b1 = Vp[(kp * 8 + 4 + t4) * 136 + nt * 8 + g];
                    mma_f16(oacc[nt], ap[kp], b0, b1);
                }
            }
            __syncthreads();
        }
    }

    // ---- row-sum reduce within warp (cols live across t4 lanes) ----
    rp0 += __shfl_xor_sync(0xffffffffu, rp0, 1);
    rp0 += __shfl_xor_sync(0xffffffffu, rp0, 2);
    rp1 += __shfl_xor_sync(0xffffffffu, rp1, 1);
    rp1 += __shfl_xor_sync(0xffffffffu, rp1, 2);
    float inv0 = 1.f / rp0, inv1 = 1.f / rp1;

    // ---- write out ----
    float* obase = out + (long)(t * HW) * DIM + h * DH;
    int qr0 = qb * 128 + warp * 16 + g, qr1 = qr0 + 8;
    #pragma unroll
    for (int nt = 0; nt < 16; nt++) {
        int d = nt * 8 + 2 * t4;
        if (qr0 < HW)
            *(float2*)(obase + (long)qr0 * DIM + d) =
                make_float2(oacc[nt][0] * inv0, oacc[nt][1] * inv0);
        if (qr1 < HW)
            *(float2*)(obase + (long)qr1 * DIM + d) =
                make_float2(oacc[nt][2] * inv1, oacc[nt][3] * inv1);
    }
}

// ---------------- launch ----------------
extern "C" void kernel_launch(void* const* d_in, const int* in_sizes, int n_in,
                              void* d_out, int out_size)
{
    const float* hidden  = (const float*)d_in[0];
    const float* history = (const float*)d_in[1];
    const float* fc   = (const float*)d_in[2];
    const float* fs   = (const float*)d_in[3];
    const float* fch  = (const float*)d_in[4];
    const float* fsh  = (const float*)d_in[5];
    const int*   sel  = (const int*)d_in[6];
    const float* Wq = (const float*)d_in[7];
    const float* bq = (const float*)d_in[8];
    const float* Wk = (const float*)d_in[9];
    const float* bk = (const float*)d_in[10];
    const float* Wv = (const float*)d_in[11];
    const float* bv = (const float*)d_in[12];
    const float* Wo = (const float*)d_in[13];
    const float* bo = (const float*)d_in[14];
    const float* gq = (const float*)d_in[15];
    const float* gk = (const float*)d_in[16];
    float* outp = (float*)d_out;

    float *qp, *kp, *vp, *ap;
    cudaGetSymbolAddress((void**)&qp, g_q);
    cudaGetSymbolAddress((void**)&kp, g_k);
    cudaGetSymbolAddress((void**)&vp, g_v);
    cudaGetSymbolAddress((void**)&ap, g_attn);

    cudaFuncSetAttribute(gemm_bias_f16,
                         cudaFuncAttributeMaxDynamicSharedMemorySize, GEMM_SMEM);
    cudaFuncSetAttribute(attention_kernel,
                         cudaFuncAttributeMaxDynamicSharedMemorySize, ATT_SMEM);

    gemm_bias_f16<<<dim3(12, 25), 256, GEMM_SMEM>>>(hidden,  Wq, bq, qp, QTOT, DIM, DIM, nullptr);
    gemm_bias_f16<<<dim3(12, 98), 256, GEMM_SMEM>>>(history, Wk, bk, kp, KTOT, DIM, DIM, sel);
    gemm_bias_f16<<<dim3(12, 98), 256, GEMM_SMEM>>>(history, Wv, bv, vp, KTOT, DIM, DIM, sel);
    rmsnorm_rope_kernel<<<QTOT, 384>>>(qp, gq, fc, fs, nullptr);
    rmsnorm_rope_kernel<<<KTOT, 384>>>(kp, gk, fch, fsh, sel);
    attention_kernel<<<dim3(13, TQ, HEADS), 256, ATT_SMEM>>>(qp, kp, vp, sel, ap);
    gemm_bias_f16<<<dim3(12, 25), 256, GEMM_SMEM>>>(ap, Wo, bo, outp, QTOT, DIM, DIM, nullptr);
}

// round 8
// speedup vs baseline: 1.8984x; 1.3391x over previous
#include <cuda_runtime.h>
#include <cuda_fp16.h>
#include <cstdint>

#define HW    1560
#define TQ    2
#define QTOT  3120
#define KTOT  12480
#define HEADS 12
#define DH    128
#define DIM   1536

// ---------------- scratch (device globals; no allocation allowed) ----------------
__device__ float g_q[QTOT * DIM];
__device__ float g_k[KTOT * DIM];
__device__ float g_v[KTOT * DIM];
__device__ float g_attn[QTOT * DIM];

// ---------------- helpers ----------------
// fp16 mma: D(4xf32) += A(4xf16x2) * B(2xf16x2)   [m16n8k16]
__device__ __forceinline__ void mma_f16(float* d, const unsigned* a, unsigned b0, unsigned b1) {
    asm volatile(
        "mma.sync.aligned.m16n8k16.row.col.f32.f16.f16.f32 "
        "{%0,%1,%2,%3}, {%4,%5,%6,%7}, {%8,%9}, {%0,%1,%2,%3};"
        : "+f"(d[0]), "+f"(d[1]), "+f"(d[2]), "+f"(d[3])
        : "r"(a[0]), "r"(a[1]), "r"(a[2]), "r"(a[3]), "r"(b0), "r"(b1));
}

__device__ __forceinline__ uint32_t smem_u32(const void* p) {
    uint32_t a;
    asm("{ .reg .u64 t; cvta.to.shared.u64 t, %1; cvt.u32.u64 %0, t; }" : "=r"(a) : "l"(p));
    return a;
}

// ldmatrix x4: four 8x8 b16 matrices; lane L supplies row address for matrix L/8, row L%8
__device__ __forceinline__ void ldsm_x4(unsigned* r, uint32_t addr) {
    asm volatile("ldmatrix.sync.aligned.m8n8.x4.shared.b16 {%0,%1,%2,%3}, [%4];"
                 : "=r"(r[0]), "=r"(r[1]), "=r"(r[2]), "=r"(r[3]) : "r"(addr));
}

__device__ __forceinline__ uint2 f4_to_h4(float4 v) {
    __half2 h0 = __float22half2_rn(make_float2(v.x, v.y));
    __half2 h1 = __float22half2_rn(make_float2(v.z, v.w));
    uint2 r;
    r.x = *(unsigned*)&h0;
    r.y = *(unsigned*)&h1;
    return r;
}

__device__ __forceinline__ bool block_needed(int b, const int* __restrict__ sel) {
    return (sel[0] == b) | (sel[1] == b) | (sel[2] == b) | (sel[3] == b);
}

// ---------------- GEMM: C[M,N] = A[M,K] @ W[N,K]^T + bias[N]  (fp16 mma, fp32 accum) ----------
// block tile 128x128x32, 256 threads = 8 warps (2M x 4N), warp tile 64x32.
// ldmatrix fragment loads; ping-pong double-buffered smem; 2 CTAs/SM.
#define GEMM_STAGE_H (128 * 40)
#define GEMM_SMEM    (2 * 2 * GEMM_STAGE_H * 2)   // 40960 bytes

__global__ __launch_bounds__(256, 2) void gemm_bias_f16(
    const float* __restrict__ A, const float* __restrict__ W,
    const float* __restrict__ bias, float* __restrict__ C,
    int M, int N, int K, const int* __restrict__ sel)
{
    extern __shared__ __half gh[];
    const int bm = blockIdx.y * 128, bn = blockIdx.x * 128;

    if (sel) {
        int b0 = bm / HW;
        int b1 = (bm + 127) / HW;
        if (!block_needed(b0, sel) && !block_needed(b1, sel)) return;
    }

    const int tid  = threadIdx.x;
    const int warp = tid >> 5, lane = tid & 31;
    const int g = lane >> 2, t4 = lane & 3;
    const int wm = warp >> 2, wn = warp & 3;

    float acc[4][4][4] = {};

    const int lc = (tid & 7) * 4;
    const int lr = tid >> 3;

    // ldmatrix per-lane addressing: matrix group i8 = lane/8, row r8 = lane%8
    const int i8 = lane >> 3, r8 = lane & 7;
    const int a_row = (i8 & 1) * 8 + r8;        // row within m16 fragment
    const int a_ko  = (i8 >> 1) * 8;            // k offset (halves)
    const uint32_t gh_b = smem_u32(gh);
    uint32_t aoff[4], boff[2];
    #pragma unroll
    for (int mt = 0; mt < 4; mt++)
        aoff[mt] = ((wm * 64 + mt * 16 + a_row) * 40 + a_ko) * 2;
    #pragma unroll
    for (int np = 0; np < 2; np++) {
        int b_row = (i8 >> 1) * 8 + r8;         // row within n16 pair
        int b_ko  = (i8 & 1) * 8;
        boff[np] = ((wn * 32 + np * 16 + b_row) * 40 + b_ko) * 2;
    }

    float4 aF[4], wF[4];
    #pragma unroll
    for (int i = 0; i < 4; i++) {
        int row = lr + 32 * i;
        long ar = bm + row;
        aF[i] = (ar < M) ? *(const float4*)(A + ar * (long)K + lc)
                         : make_float4(0.f, 0.f, 0.f, 0.f);
        wF[i] = *(const float4*)(W + (long)(bn + row) * K + lc);
    }

    {
        __half* As = gh;
        __half* Ws = gh + GEMM_STAGE_H;
        #pragma unroll
        for (int i = 0; i < 4; i++) {
            int row = lr + 32 * i;
            *(uint2*)&As[row * 40 + lc] = f4_to_h4(aF[i]);
            *(uint2*)&Ws[row * 40 + lc] = f4_to_h4(wF[i]);
        }
    }
    __syncthreads();

    const int KT = K >> 5;
    for (int kt = 0; kt < KT; kt++) {
        const uint32_t As_b = gh_b + (kt & 1) * (4 * GEMM_STAGE_H);  // bytes
        const uint32_t Ws_b = As_b + 2 * GEMM_STAGE_H;

        if (kt + 1 < KT) {
            int k0 = (kt + 1) << 5;
            #pragma unroll
            for (int i = 0; i < 4; i++) {
                int row = lr + 32 * i;
                long ar = bm + row;
                aF[i] = (ar < M) ? *(const float4*)(A + ar * (long)K + k0 + lc)
                                 : make_float4(0.f, 0.f, 0.f, 0.f);
                wF[i] = *(const float4*)(W + (long)(bn + row) * K + k0 + lc);
            }
        }

        #pragma unroll
        for (int kk = 0; kk < 2; kk++) {
            const uint32_t kB = kk * 32;   // 16 halves = 32 bytes
            unsigned a[4][4], b[2][4];
            #pragma unroll
            for (int mt = 0; mt < 4; mt++) ldsm_x4(a[mt], As_b + aoff[mt] + kB);
            #pragma unroll
            for (int np = 0; np < 2; np++) ldsm_x4(b[np], Ws_b + boff[np] + kB);
            #pragma unroll
            for (int nt = 0; nt < 4; nt++) {
                unsigned b0 = b[nt >> 1][(nt & 1) * 2];
                unsigned b1 = b[nt >> 1][(nt & 1) * 2 + 1];
                #pragma unroll
                for (int mt = 0; mt < 4; mt++)
                    mma_f16(acc[mt][nt], a[mt], b0, b1);
            }
        }

        if (kt + 1 < KT) {
            __half* Asn = gh + ((kt + 1) & 1) * 2 * GEMM_STAGE_H;
            __half* Wsn = Asn + GEMM_STAGE_H;
            #pragma unroll
            for (int i = 0; i < 4; i++) {
                int row = lr + 32 * i;
                *(uint2*)&Asn[row * 40 + lc] = f4_to_h4(aF[i]);
                *(uint2*)&Wsn[row * 40 + lc] = f4_to_h4(wF[i]);
            }
        }
        __syncthreads();
    }

    #pragma unroll
    for (int mt = 0; mt < 4; mt++) {
        int r = bm + wm * 64 + mt * 16 + g;
        #pragma unroll
        for (int nt = 0; nt < 4; nt++) {
            int c = bn + wn * 32 + nt * 8 + t4 * 2;
            float b0 = bias[c], b1 = bias[c + 1];
            if (r < M)
                *(float2*)(C + (long)r * N + c) =
                    make_float2(acc[mt][nt][0] + b0, acc[mt][nt][1] + b1);
            if (r + 8 < M)
                *(float2*)(C + (long)(r + 8) * N + c) =
                    make_float2(acc[mt][nt][2] + b0, acc[mt][nt][3] + b1);
        }
    }
}

// ---------------- fused RMSNorm + RoPE (in-place, one row per CTA) ----------------
__global__ __launch_bounds__(384) void rmsnorm_rope_kernel(
    float* __restrict__ x, const float* __restrict__ gamma,
    const float* __restrict__ fc, const float* __restrict__ fs,
    const int* __restrict__ sel)
{
    __shared__ float red[12];
    __shared__ float rinv_s;
    const int row = blockIdx.x, tid = threadIdx.x;

    if (sel && !block_needed(row / HW, sel)) return;

    float4 v = *(float4*)(x + (long)row * DIM + tid * 4);
    float ss = v.x * v.x + v.y * v.y + v.z * v.z + v.w * v.w;
    #pragma unroll
    for (int s = 16; s > 0; s >>= 1) ss += __shfl_xor_sync(0xffffffffu, ss, s);
    if ((tid & 31) == 0) red[tid >> 5] = ss;
    __syncthreads();
    if (tid < 32) {
        float t = (tid < 12) ? red[tid] : 0.f;
        #pragma unroll
        for (int s = 16; s > 0; s >>= 1) t += __shfl_xor_sync(0xffffffffu, t, s);
        if (tid == 0) rinv_s = rsqrtf(t * (1.0f / DIM) + 1e-5f);
    }
    __syncthreads();
    float r = rinv_s;

    float4 g4 = *(const float4*)(gamma + tid * 4);
    float x0 = v.x * r * g4.x, x1 = v.y * r * g4.y;
    float x2 = v.z * r * g4.z, x3 = v.w * r * g4.w;

    int hd = (tid * 4) & (DH - 1);
    float4 c4 = *(const float4*)(fc + (long)row * DH + hd);
    float4 s4 = *(const float4*)(fs + (long)row * DH + hd);
    float4 o;
    o.x = x0 * c4.x - x1 * s4.y;
    o.y = x0 * s4.y + x1 * c4.x;
    o.z = x2 * c4.z - x3 * s4.w;
    o.w = x2 * s4.w + x3 * c4.z;
    *(float4*)(x + (long)row * DIM + tid * 4) = o;
}

// ---------------- fused block-sparse attention (register-P, all-fp16 mma, ldmatrix QK) ----
#define AQ_OFF  0                        // half  [128][136]  34816 B
#define AK_OFF  34816                    // half  [64][136]   17408 B
#define AV_OFF  52224                    // uint  [32 pairs][136]  17408 B
#define ATT_SMEM 69632

__global__ __launch_bounds__(256, 2) void attention_kernel(
    const float* __restrict__ q, const float* __restrict__ k,
    const float* __restrict__ v, const int* __restrict__ sel,
    float* __restrict__ out)
{
    extern __shared__ char asm_[];
    __half*   Qh = (__half*)(asm_ + AQ_OFF);   // [128][136]
    __half*   Kh = (__half*)(asm_ + AK_OFF);   // [64][136]
    unsigned* Vp = (unsigned*)(asm_ + AV_OFF); // [32][136] half2(V[2p][d], V[2p+1][d])

    const int qb = blockIdx.x, t = blockIdx.y, h = blockIdx.z;
    const int tid = threadIdx.x, warp = tid >> 5, lane = tid & 31;
    const int g = lane >> 2, t4 = lane & 3;

    // ldmatrix per-lane addressing
    const int i8 = lane >> 3, r8 = lane & 7;
    const uint32_t Qh_b = smem_u32(asm_) + AQ_OFF;
    const uint32_t Kh_b = smem_u32(asm_) + AK_OFF;
    const uint32_t qoff = ((warp * 16 + (i8 & 1) * 8 + r8) * 136 + (i8 >> 1) * 8) * 2;
    uint32_t koff_[4];
    #pragma unroll
    for (int np = 0; np < 4; np++)
        koff_[np] = ((np * 16 + (i8 >> 1) * 8 + r8) * 136 + (i8 & 1) * 8) * 2;

    // load Q tile (fp16, zero-fill tail rows)
    const float* qbase = q + (long)(t * HW) * DIM + (long)h * DH;
    {
        const int c4 = (tid & 31) * 4;
        const int lr0 = tid >> 5;
        #pragma unroll
        for (int i = 0; i < 16; i++) {
            int r = lr0 + i * 8;
            int qr = qb * 128 + r;
            float4 val = (qr < HW) ? *(const float4*)(qbase + (long)qr * DIM + c4)
                                   : make_float4(0.f, 0.f, 0.f, 0.f);
            *(uint2*)&Qh[r * 136 + c4] = f4_to_h4(val);
        }
    }

    float oacc[16][4] = {};
    float rp0 = 0.f, rp1 = 0.f;

    int s0 = sel[t * 2 + 0]; if (s0 < 0) s0 = 0;
    int s1 = sel[t * 2 + 1];
    int nb = (s1 >= 0) ? 2 : 1;

    __syncthreads();

    const float SC   = 0.08838834764831843f * 1.4426950408889634f;
    const float OFFL = 4.0f * 1.4426950408889634f;

    for (int bi = 0; bi < nb; bi++) {
        int blk = (bi == 0) ? s0 : s1;
        const float* kbp = k + (long)blk * HW * DIM + (long)h * DH;
        const float* vbp = v + (long)blk * HW * DIM + (long)h * DH;

        for (int n0 = 0; n0 < HW; n0 += 64) {
            // ---- load K tile (fp16) ----
            {
                const int c4 = (tid & 31) * 4;
                const int lr0 = tid >> 5;
                #pragma unroll
                for (int i = 0; i < 8; i++) {
                    int r = lr0 + i * 8;
                    int kr = n0 + r;
                    float4 kv = (kr < HW) ? *(const float4*)(kbp + (long)kr * DIM + c4)
                                          : make_float4(0.f, 0.f, 0.f, 0.f);
                    *(uint2*)&Kh[r * 136 + c4] = f4_to_h4(kv);
                }
            }
            // ---- load V tile, key-pair interleaved ----
            #pragma unroll
            for (int i = 0; i < 4; i++) {
                int idx = i * 256 + tid;
                int p = idx >> 5;
                int d = (idx & 31) * 4;
                int kr0 = n0 + 2 * p;
                float4 v0 = (kr0 < HW)     ? *(const float4*)(vbp + (long)kr0 * DIM + d)
                                           : make_float4(0.f, 0.f, 0.f, 0.f);
                float4 v1 = (kr0 + 1 < HW) ? *(const float4*)(vbp + (long)(kr0 + 1) * DIM + d)
                                           : make_float4(0.f, 0.f, 0.f, 0.f);
                __half2 h0 = __floats2half2_rn(v0.x, v1.x);
                __half2 h1 = __floats2half2_rn(v0.y, v1.y);
                __half2 h2 = __floats2half2_rn(v0.z, v1.z);
                __half2 h3 = __floats2half2_rn(v0.w, v1.w);
                *(uint2*)&Vp[p * 136 + d]     = make_uint2(*(unsigned*)&h0, *(unsigned*)&h1);
                *(uint2*)&Vp[p * 136 + d + 2] = make_uint2(*(unsigned*)&h2, *(unsigned*)&h3);
            }
            __syncthreads();

            // ---- QK^T via ldmatrix: rows warp*16..+16 x 64 keys ----
            float sacc[8][4] = {};
            #pragma unroll
            for (int ks = 0; ks < 8; ks++) {
                const uint32_t kB = ks * 32;
                unsigned a[4], b[4][4];
                ldsm_x4(a, Qh_b + qoff + kB);
                #pragma unroll
                for (int np = 0; np < 4; np++) ldsm_x4(b[np], Kh_b + koff_[np] + kB);
                #pragma unroll
                for (int nt = 0; nt < 8; nt++) {
                    unsigned b0 = b[nt >> 1][(nt & 1) * 2];
                    unsigned b1 = b[nt >> 1][(nt & 1) * 2 + 1];
                    mma_f16(sacc[nt], a, b0, b1);
                }
            }

            // ---- softmax numerators in regs; P fragments = PV A-fragments ----
            unsigned ap[4][4];
            #pragma unroll
            for (int nt = 0; nt < 8; nt++) {
                int cn = nt * 8 + 2 * t4;
                bool m0 = (n0 + cn) < HW, m1 = (n0 + cn + 1) < HW;
                float p0 = m0 ? exp2f(fmaf(sacc[nt][0], SC, -OFFL)) : 0.f;
                float p1 = m1 ? exp2f(fmaf(sacc[nt][1], SC, -OFFL)) : 0.f;
                float p2 = m0 ? exp2f(fmaf(sacc[nt][2], SC, -OFFL)) : 0.f;
                float p3 = m1 ? exp2f(fmaf(sacc[nt][3], SC, -OFFL)) : 0.f;
                rp0 += p0 + p1;
                rp1 += p2 + p3;
                __half2 h01 = __floats2half2_rn(p0, p1);
                __half2 h23 = __floats2half2_rn(p2, p3);
                ap[nt >> 1][(nt & 1) * 2 + 0] = *(unsigned*)&h01;
                ap[nt >> 1][(nt & 1) * 2 + 1] = *(unsigned*)&h23;
            }

            // ---- P @ V ----
            #pragma unroll
            for (int kp = 0; kp < 4; kp++) {
                #pragma unroll
                for (int nt = 0; nt < 16; nt++) {
                    unsigned b0 = Vp[(kp * 8 + t4) * 136 + nt * 8 + g];
                    unsigned b1 = Vp[(kp * 8 + 4 + t4) * 136 + nt * 8 + g];
                    mma_f16(oacc[nt], ap[kp], b0, b1);
                }
            }
            __syncthreads();
        }
    }

    // ---- row-sum reduce within warp ----
    rp0 += __shfl_xor_sync(0xffffffffu, rp0, 1);
    rp0 += __shfl_xor_sync(0xffffffffu, rp0, 2);
    rp1 += __shfl_xor_sync(0xffffffffu, rp1, 1);
    rp1 += __shfl_xor_sync(0xffffffffu, rp1, 2);
    float inv0 = 1.f / rp0, inv1 = 1.f / rp1;

    // ---- write out ----
    float* obase = out + (long)(t * HW) * DIM + h * DH;
    int qr0 = qb * 128 + warp * 16 + g, qr1 = qr0 + 8;
    #pragma unroll
    for (int nt = 0; nt < 16; nt++) {
        int d = nt * 8 + 2 * t4;
        if (qr0 < HW)
            *(float2*)(obase + (long)qr0 * DIM + d) =
                make_float2(oacc[nt][0] * inv0, oacc[nt][1] * inv0);
        if (qr1 < HW)
            *(float2*)(obase + (long)qr1 * DIM + d) =
                make_float2(oacc[nt][2] * inv1, oacc[nt][3] * inv1);
    }
}

// ---------------- launch ----------------
extern "C" void kernel_launch(void* const* d_in, const int* in_sizes, int n_in,
                              void* d_out, int out_size)
{
    const float* hidden  = (const float*)d_in[0];
    const float* history = (const float*)d_in[1];
    const float* fc   = (const float*)d_in[2];
    const float* fs   = (const float*)d_in[3];
    const float* fch  = (const float*)d_in[4];
    const float* fsh  = (const float*)d_in[5];
    const int*   sel  = (const int*)d_in[6];
    const float* Wq = (const float*)d_in[7];
    const float* bq = (const float*)d_in[8];
    const float* Wk = (const float*)d_in[9];
    const float* bk = (const float*)d_in[10];
    const float* Wv = (const float*)d_in[11];
    const float* bv = (const float*)d_in[12];
    const float* Wo = (const float*)d_in[13];
    const float* bo = (const float*)d_in[14];
    const float* gq = (const float*)d_in[15];
    const float* gk = (const float*)d_in[16];
    float* outp = (float*)d_out;

    float *qp, *kp, *vp, *ap;
    cudaGetSymbolAddress((void**)&qp, g_q);
    cudaGetSymbolAddress((void**)&kp, g_k);
    cudaGetSymbolAddress((void**)&vp, g_v);
    cudaGetSymbolAddress((void**)&ap, g_attn);

    cudaFuncSetAttribute(gemm_bias_f16,
                         cudaFuncAttributeMaxDynamicSharedMemorySize, GEMM_SMEM);
    cudaFuncSetAttribute(attention_kernel,
                         cudaFuncAttributeMaxDynamicSharedMemorySize, ATT_SMEM);

    gemm_bias_f16<<<dim3(12, 25), 256, GEMM_SMEM>>>(hidden,  Wq, bq, qp, QTOT, DIM, DIM, nullptr);
    gemm_bias_f16<<<dim3(12, 98), 256, GEMM_SMEM>>>(history, Wk, bk, kp, KTOT, DIM, DIM, sel);
    gemm_bias_f16<<<dim3(12, 98), 256, GEMM_SMEM>>>(history, Wv, bv, vp, KTOT, DIM, DIM, sel);
    rmsnorm_rope_kernel<<<QTOT, 384>>>(qp, gq, fc, fs, nullptr);
    rmsnorm_rope_kernel<<<KTOT, 384>>>(kp, gk, fch, fsh, sel);
    attention_kernel<<<dim3(13, TQ, HEADS), 256, ATT_SMEM>>>(qp, kp, vp, sel, ap);
    gemm_bias_f16<<<dim3(12, 25), 256, GEMM_SMEM>>>(ap, Wo, bo, outp, QTOT, DIM, DIM, nullptr);
}

// round 9
// speedup vs baseline: 2.0228x; 1.0655x over previous
#include <cuda_runtime.h>
#include <cuda_fp16.h>
#include <cstdint>

#define HW    1560
#define TQ    2
#define QTOT  3120
#define KTOT  12480
#define HEADS 12
#define DH    128
#define DIM   1536

// ---------------- scratch (device globals; no allocation allowed) ----------------
__device__ __half g_q[QTOT * DIM];
__device__ __half g_k[KTOT * DIM];
__device__ __half g_v[KTOT * DIM];
__device__ __half g_attn[QTOT * DIM];

// ---------------- helpers ----------------
// fp16 mma: D(4xf32) += A(4xf16x2) * B(2xf16x2)   [m16n8k16]
__device__ __forceinline__ void mma_f16(float* d, const unsigned* a, unsigned b0, unsigned b1) {
    asm volatile(
        "mma.sync.aligned.m16n8k16.row.col.f32.f16.f16.f32 "
        "{%0,%1,%2,%3}, {%4,%5,%6,%7}, {%8,%9}, {%0,%1,%2,%3};"
        : "+f"(d[0]), "+f"(d[1]), "+f"(d[2]), "+f"(d[3])
        : "r"(a[0]), "r"(a[1]), "r"(a[2]), "r"(a[3]), "r"(b0), "r"(b1));
}

__device__ __forceinline__ uint32_t smem_u32(const void* p) {
    uint32_t a;
    asm("{ .reg .u64 t; cvta.to.shared.u64 t, %1; cvt.u32.u64 %0, t; }" : "=r"(a) : "l"(p));
    return a;
}

__device__ __forceinline__ void ldsm_x4(unsigned* r, uint32_t addr) {
    asm volatile("ldmatrix.sync.aligned.m8n8.x4.shared.b16 {%0,%1,%2,%3}, [%4];"
                 : "=r"(r[0]), "=r"(r[1]), "=r"(r[2]), "=r"(r[3]) : "r"(addr));
}

__device__ __forceinline__ uint2 f4_to_h4(float4 v) {
    __half2 h0 = __float22half2_rn(make_float2(v.x, v.y));
    __half2 h1 = __float22half2_rn(make_float2(v.z, v.w));
    uint2 r;
    r.x = *(unsigned*)&h0;
    r.y = *(unsigned*)&h1;
    return r;
}

__device__ __forceinline__ bool block_needed(int b, const int* __restrict__ sel) {
    return (sel[0] == b) | (sel[1] == b) | (sel[2] == b) | (sel[3] == b);
}

// ---------------- GEMM: C[M,N] = A[M,K] @ W[N,K]^T + bias[N]  (fp16 mma, fp32 accum) ----------
// block tile 128x128x32, 256 threads = 8 warps (2M x 4N), warp tile 64x32.
// ldmatrix fragment loads; ping-pong double-buffered smem; 2 CTAs/SM.
// IN_HALF: A is __half (no convert in producer). OUT_HALF: C written as __half.
#define GEMM_STAGE_H (128 * 40)
#define GEMM_SMEM    (2 * 2 * GEMM_STAGE_H * 2)   // 40960 bytes

template <bool IN_HALF, bool OUT_HALF>
__global__ __launch_bounds__(256, 2) void gemm_bias_f16(
    const void* __restrict__ Av, const float* __restrict__ W,
    const float* __restrict__ bias, void* __restrict__ Cv,
    int M, int N, int K, const int* __restrict__ sel)
{
    extern __shared__ __half gh[];
    const float*  Af = (const float*)Av;
    const __half* Ah = (const __half*)Av;
    float*  Cf = (float*)Cv;
    __half* Ch = (__half*)Cv;

    const int bm = blockIdx.y * 128, bn = blockIdx.x * 128;

    if (sel) {
        int b0 = bm / HW;
        int b1 = (bm + 127) / HW;
        if (!block_needed(b0, sel) && !block_needed(b1, sel)) return;
    }

    const int tid  = threadIdx.x;
    const int warp = tid >> 5, lane = tid & 31;
    const int g = lane >> 2, t4 = lane & 3;
    const int wm = warp >> 2, wn = warp & 3;

    float acc[4][4][4] = {};

    // fp32-input producer indexing (A and W): 16B = 4 floats
    const int lc = (tid & 7) * 4;   // float col
    const int lr = tid >> 3;        // rows lr + 32*i
    // fp16-input producer indexing (A only): 16B = 8 halves
    const int lc2 = (tid & 3) * 8;  // half col
    const int lr2 = tid >> 2;       // rows lr2 + 64*i

    // ldmatrix per-lane addressing
    const int i8 = lane >> 3, r8 = lane & 7;
    const int a_row = (i8 & 1) * 8 + r8;
    const int a_ko  = (i8 >> 1) * 8;
    const uint32_t gh_b = smem_u32(gh);
    uint32_t aoff[4], boff[2];
    #pragma unroll
    for (int mt = 0; mt < 4; mt++)
        aoff[mt] = ((wm * 64 + mt * 16 + a_row) * 40 + a_ko) * 2;
    #pragma unroll
    for (int np = 0; np < 2; np++) {
        int b_row = (i8 >> 1) * 8 + r8;
        int b_ko  = (i8 & 1) * 8;
        boff[np] = ((wn * 32 + np * 16 + b_row) * 40 + b_ko) * 2;
    }

    float4 aF[4], wF[4];
    uint4  aH[2];
    const uint4 z4 = make_uint4(0u, 0u, 0u, 0u);

    // prefetch k-tile 0
    if (IN_HALF) {
        #pragma unroll
        for (int i = 0; i < 2; i++) {
            int row = lr2 + 64 * i;
            long ar = bm + row;
            aH[i] = (ar < M) ? *(const uint4*)(Ah + ar * (long)K + lc2) : z4;
        }
    } else {
        #pragma unroll
        for (int i = 0; i < 4; i++) {
            int row = lr + 32 * i;
            long ar = bm + row;
            aF[i] = (ar < M) ? *(const float4*)(Af + ar * (long)K + lc)
                             : make_float4(0.f, 0.f, 0.f, 0.f);
        }
    }
    #pragma unroll
    for (int i = 0; i < 4; i++) {
        int row = lr + 32 * i;
        wF[i] = *(const float4*)(W + (long)(bn + row) * K + lc);
    }

    // prime stage 0
    {
        __half* As = gh;
        __half* Ws = gh + GEMM_STAGE_H;
        if (IN_HALF) {
            #pragma unroll
            for (int i = 0; i < 2; i++) {
                int row = lr2 + 64 * i;
                *(uint4*)&As[row * 40 + lc2] = aH[i];
            }
        } else {
            #pragma unroll
            for (int i = 0; i < 4; i++) {
                int row = lr + 32 * i;
                *(uint2*)&As[row * 40 + lc] = f4_to_h4(aF[i]);
            }
        }
        #pragma unroll
        for (int i = 0; i < 4; i++) {
            int row = lr + 32 * i;
            *(uint2*)&Ws[row * 40 + lc] = f4_to_h4(wF[i]);
        }
    }
    __syncthreads();

    const int KT = K >> 5;
    for (int kt = 0; kt < KT; kt++) {
        const uint32_t As_b = gh_b + (kt & 1) * (4 * GEMM_STAGE_H);  // bytes
        const uint32_t Ws_b = As_b + 2 * GEMM_STAGE_H;

        if (kt + 1 < KT) {
            int k0 = (kt + 1) << 5;
            if (IN_HALF) {
                #pragma unroll
                for (int i = 0; i < 2; i++) {
                    int row = lr2 + 64 * i;
                    long ar = bm + row;
                    aH[i] = (ar < M) ? *(const uint4*)(Ah + ar * (long)K + k0 + lc2) : z4;
                }
            } else {
                #pragma unroll
                for (int i = 0; i < 4; i++) {
                    int row = lr + 32 * i;
                    long ar = bm + row;
                    aF[i] = (ar < M) ? *(const float4*)(Af + ar * (long)K + k0 + lc)
                                     : make_float4(0.f, 0.f, 0.f, 0.f);
                }
            }
            #pragma unroll
            for (int i = 0; i < 4; i++) {
                int row = lr + 32 * i;
                wF[i] = *(const float4*)(W + (long)(bn + row) * K + k0 + lc);
            }
        }

        #pragma unroll
        for (int kk = 0; kk < 2; kk++) {
            const uint32_t kB = kk * 32;
            unsigned a[4][4], b[2][4];
            #pragma unroll
            for (int mt = 0; mt < 4; mt++) ldsm_x4(a[mt], As_b + aoff[mt] + kB);
            #pragma unroll
            for (int np = 0; np < 2; np++) ldsm_x4(b[np], Ws_b + boff[np] + kB);
            #pragma unroll
            for (int nt = 0; nt < 4; nt++) {
                unsigned b0 = b[nt >> 1][(nt & 1) * 2];
                unsigned b1 = b[nt >> 1][(nt & 1) * 2 + 1];
                #pragma unroll
                for (int mt = 0; mt < 4; mt++)
                    mma_f16(acc[mt][nt], a[mt], b0, b1);
            }
        }

        if (kt + 1 < KT) {
            __half* Asn = gh + ((kt + 1) & 1) * 2 * GEMM_STAGE_H;
            __half* Wsn = Asn + GEMM_STAGE_H;
            if (IN_HALF) {
                #pragma unroll
                for (int i = 0; i < 2; i++) {
                    int row = lr2 + 64 * i;
                    *(uint4*)&Asn[row * 40 + lc2] = aH[i];
                }
            } else {
                #pragma unroll
                for (int i = 0; i < 4; i++) {
                    int row = lr + 32 * i;
                    *(uint2*)&Asn[row * 40 + lc] = f4_to_h4(aF[i]);
                }
            }
            #pragma unroll
            for (int i = 0; i < 4; i++) {
                int row = lr + 32 * i;
                *(uint2*)&Wsn[row * 40 + lc] = f4_to_h4(wF[i]);
            }
        }
        __syncthreads();
    }

    #pragma unroll
    for (int mt = 0; mt < 4; mt++) {
        int r = bm + wm * 64 + mt * 16 + g;
        #pragma unroll
        for (int nt = 0; nt < 4; nt++) {
            int c = bn + wn * 32 + nt * 8 + t4 * 2;
            float b0 = bias[c], b1 = bias[c + 1];
            if (OUT_HALF) {
                if (r < M) {
                    __half2 h = __floats2half2_rn(acc[mt][nt][0] + b0, acc[mt][nt][1] + b1);
                    *(unsigned*)(Ch + (long)r * N + c) = *(unsigned*)&h;
                }
                if (r + 8 < M) {
                    __half2 h = __floats2half2_rn(acc[mt][nt][2] + b0, acc[mt][nt][3] + b1);
                    *(unsigned*)(Ch + (long)(r + 8) * N + c) = *(unsigned*)&h;
                }
            } else {
                if (r < M)
                    *(float2*)(Cf + (long)r * N + c) =
                        make_float2(acc[mt][nt][0] + b0, acc[mt][nt][1] + b1);
                if (r + 8 < M)
                    *(float2*)(Cf + (long)(r + 8) * N + c) =
                        make_float2(acc[mt][nt][2] + b0, acc[mt][nt][3] + b1);
            }
        }
    }
}

// ---------------- fused RMSNorm + RoPE (in-place on fp16 buffer, one row per CTA) -------------
__global__ __launch_bounds__(384) void rmsnorm_rope_kernel(
    __half* __restrict__ x, const float* __restrict__ gamma,
    const float* __restrict__ fc, const float* __restrict__ fs,
    const int* __restrict__ sel)
{
    __shared__ float red[12];
    __shared__ float rinv_s;
    const int row = blockIdx.x, tid = threadIdx.x;

    if (sel && !block_needed(row / HW, sel)) return;

    uint2 u = *(uint2*)(x + (long)row * DIM + tid * 4);
    __half2 h01 = *(__half2*)&u.x;
    __half2 h23 = *(__half2*)&u.y;
    float2 f01 = __half22float2(h01);
    float2 f23 = __half22float2(h23);

    float ss = f01.x * f01.x + f01.y * f01.y + f23.x * f23.x + f23.y * f23.y;
    #pragma unroll
    for (int s = 16; s > 0; s >>= 1) ss += __shfl_xor_sync(0xffffffffu, ss, s);
    if ((tid & 31) == 0) red[tid >> 5] = ss;
    __syncthreads();
    if (tid < 32) {
        float t = (tid < 12) ? red[tid] : 0.f;
        #pragma unroll
        for (int s = 16; s > 0; s >>= 1) t += __shfl_xor_sync(0xffffffffu, t, s);
        if (tid == 0) rinv_s = rsqrtf(t * (1.0f / DIM) + 1e-5f);
    }
    __syncthreads();
    float r = rinv_s;

    float4 g4 = *(const float4*)(gamma + tid * 4);
    float x0 = f01.x * r * g4.x, x1 = f01.y * r * g4.y;
    float x2 = f23.x * r * g4.z, x3 = f23.y * r * g4.w;

    int hd = (tid * 4) & (DH - 1);
    float4 c4 = *(const float4*)(fc + (long)row * DH + hd);
    float4 s4 = *(const float4*)(fs + (long)row * DH + hd);
    float o0 = x0 * c4.x - x1 * s4.y;
    float o1 = x0 * s4.y + x1 * c4.x;
    float o2 = x2 * c4.z - x3 * s4.w;
    float o3 = x2 * s4.w + x3 * c4.z;

    __half2 ho01 = __floats2half2_rn(o0, o1);
    __half2 ho23 = __floats2half2_rn(o2, o3);
    *(uint2*)(x + (long)row * DIM + tid * 4) =
        make_uint2(*(unsigned*)&ho01, *(unsigned*)&ho23);
}

// ---------------- fused block-sparse attention (register-P, all-fp16, ldmatrix QK) ------------
#define AQ_OFF  0                        // half  [128][136]  34816 B
#define AK_OFF  34816                    // half  [64][136]   17408 B
#define AV_OFF  52224                    // uint  [32 pairs][136]  17408 B
#define ATT_SMEM 69632

__global__ __launch_bounds__(256, 2) void attention_kernel(
    const __half* __restrict__ q, const __half* __restrict__ k,
    const __half* __restrict__ v, const int* __restrict__ sel,
    __half* __restrict__ out)
{
    extern __shared__ char asm_[];
    __half*   Qh = (__half*)(asm_ + AQ_OFF);   // [128][136]
    __half*   Kh = (__half*)(asm_ + AK_OFF);   // [64][136]
    unsigned* Vp = (unsigned*)(asm_ + AV_OFF); // [32][136] half2(V[2p][d], V[2p+1][d])

    const int qb = blockIdx.x, t = blockIdx.y, h = blockIdx.z;
    const int tid = threadIdx.x, warp = tid >> 5, lane = tid & 31;
    const int g = lane >> 2, t4 = lane & 3;

    const int i8 = lane >> 3, r8 = lane & 7;
    const uint32_t Qh_b = smem_u32(asm_) + AQ_OFF;
    const uint32_t Kh_b = smem_u32(asm_) + AK_OFF;
    const uint32_t qoff = ((warp * 16 + (i8 & 1) * 8 + r8) * 136 + (i8 >> 1) * 8) * 2;
    uint32_t koff_[4];
    #pragma unroll
    for (int np = 0; np < 4; np++)
        koff_[np] = ((np * 16 + (i8 >> 1) * 8 + r8) * 136 + (i8 & 1) * 8) * 2;

    const uint4 z4 = make_uint4(0u, 0u, 0u, 0u);

    // load Q tile (already fp16; direct 16B copies, zero-fill tail rows)
    const __half* qbase = q + (long)(t * HW) * DIM + (long)h * DH;
    {
        const int c8 = (tid & 15) * 8;
        const int lr0 = tid >> 4;
        #pragma unroll
        for (int i = 0; i < 8; i++) {
            int r = lr0 + i * 16;
            int qr = qb * 128 + r;
            uint4 val = (qr < HW) ? *(const uint4*)(qbase + (long)qr * DIM + c8) : z4;
            *(uint4*)&Qh[r * 136 + c8] = val;
        }
    }

    float oacc[16][4] = {};
    float rp0 = 0.f, rp1 = 0.f;

    int s0 = sel[t * 2 + 0]; if (s0 < 0) s0 = 0;
    int s1 = sel[t * 2 + 1];
    int nb = (s1 >= 0) ? 2 : 1;

    __syncthreads();

    const float SC   = 0.08838834764831843f * 1.4426950408889634f;
    const float OFFL = 4.0f * 1.4426950408889634f;

    for (int bi = 0; bi < nb; bi++) {
        int blk = (bi == 0) ? s0 : s1;
        const __half* kbp = k + (long)blk * HW * DIM + (long)h * DH;
        const __half* vbp = v + (long)blk * HW * DIM + (long)h * DH;

        for (int n0 = 0; n0 < HW; n0 += 64) {
            // ---- load K tile (direct fp16 copies) ----
            {
                const int c8 = (tid & 15) * 8;
                const int lr0 = tid >> 4;
                #pragma unroll
                for (int i = 0; i < 4; i++) {
                    int r = lr0 + i * 16;
                    int kr = n0 + r;
                    uint4 kv = (kr < HW) ? *(const uint4*)(kbp + (long)kr * DIM + c8) : z4;
                    *(uint4*)&Kh[r * 136 + c8] = kv;
                }
            }
            // ---- load V tile, key-pair interleaved ----
            #pragma unroll
            for (int i = 0; i < 2; i++) {
                int idx = i * 256 + tid;
                int p = idx >> 4;            // pair 0..31
                int dc = (idx & 15) * 8;     // dim chunk of 8
                int kr0 = n0 + 2 * p;
                uint4 u0 = (kr0 < HW)     ? *(const uint4*)(vbp + (long)kr0 * DIM + dc) : z4;
                uint4 u1 = (kr0 + 1 < HW) ? *(const uint4*)(vbp + (long)(kr0 + 1) * DIM + dc) : z4;
                const __half* a0 = (const __half*)&u0;
                const __half* a1 = (const __half*)&u1;
                unsigned o[8];
                #pragma unroll
                for (int j = 0; j < 8; j++) {
                    __half2 hj = __halves2half2(a0[j], a1[j]);
                    o[j] = *(unsigned*)&hj;
                }
                *(uint4*)&Vp[p * 136 + dc]     = make_uint4(o[0], o[1], o[2], o[3]);
                *(uint4*)&Vp[p * 136 + dc + 4] = make_uint4(o[4], o[5], o[6], o[7]);
            }
            __syncthreads();

            // ---- QK^T via ldmatrix ----
            float sacc[8][4] = {};
            #pragma unroll
            for (int ks = 0; ks < 8; ks++) {
                const uint32_t kB = ks * 32;
                unsigned a[4], b[4][4];
                ldsm_x4(a, Qh_b + qoff + kB);
                #pragma unroll
                for (int np = 0; np < 4; np++) ldsm_x4(b[np], Kh_b + koff_[np] + kB);
                #pragma unroll
                for (int nt = 0; nt < 8; nt++) {
                    unsigned b0 = b[nt >> 1][(nt & 1) * 2];
                    unsigned b1 = b[nt >> 1][(nt & 1) * 2 + 1];
                    mma_f16(sacc[nt], a, b0, b1);
                }
            }

            // ---- softmax numerators in regs; P fragments = PV A-fragments ----
            unsigned ap[4][4];
            #pragma unroll
            for (int nt = 0; nt < 8; nt++) {
                int cn = nt * 8 + 2 * t4;
                bool m0 = (n0 + cn) < HW, m1 = (n0 + cn + 1) < HW;
                float p0 = m0 ? exp2f(fmaf(sacc[nt][0], SC, -OFFL)) : 0.f;
                float p1 = m1 ? exp2f(fmaf(sacc[nt][1], SC, -OFFL)) : 0.f;
                float p2 = m0 ? exp2f(fmaf(sacc[nt][2], SC, -OFFL)) : 0.f;
                float p3 = m1 ? exp2f(fmaf(sacc[nt][3], SC, -OFFL)) : 0.f;
                rp0 += p0 + p1;
                rp1 += p2 + p3;
                __half2 h01 = __floats2half2_rn(p0, p1);
                __half2 h23 = __floats2half2_rn(p2, p3);
                ap[nt >> 1][(nt & 1) * 2 + 0] = *(unsigned*)&h01;
                ap[nt >> 1][(nt & 1) * 2 + 1] = *(unsigned*)&h23;
            }

            // ---- P @ V ----
            #pragma unroll
            for (int kp = 0; kp < 4; kp++) {
                #pragma unroll
                for (int nt = 0; nt < 16; nt++) {
                    unsigned b0 = Vp[(kp * 8 + t4) * 136 + nt * 8 + g];
                    unsigned b1 = Vp[(kp * 8 + 4 + t4) * 136 + nt * 8 + g];
                    mma_f16(oacc[nt], ap[kp], b0, b1);
                }
            }
            __syncthreads();
        }
    }

    // ---- row-sum reduce within warp ----
    rp0 += __shfl_xor_sync(0xffffffffu, rp0, 1);
    rp0 += __shfl_xor_sync(0xffffffffu, rp0, 2);
    rp1 += __shfl_xor_sync(0xffffffffu, rp1, 1);
    rp1 += __shfl_xor_sync(0xffffffffu, rp1, 2);
    float inv0 = 1.f / rp0, inv1 = 1.f / rp1;

    // ---- write out (fp16) ----
    __half* obase = out + (long)(t * HW) * DIM + h * DH;
    int qr0 = qb * 128 + warp * 16 + g, qr1 = qr0 + 8;
    #pragma unroll
    for (int nt = 0; nt < 16; nt++) {
        int d = nt * 8 + 2 * t4;
        if (qr0 < HW) {
            __half2 h = __floats2half2_rn(oacc[nt][0] * inv0, oacc[nt][1] * inv0);
            *(unsigned*)(obase + (long)qr0 * DIM + d) = *(unsigned*)&h;
        }
        if (qr1 < HW) {
            __half2 h = __floats2half2_rn(oacc[nt][2] * inv1, oacc[nt][3] * inv1);
            *(unsigned*)(obase + (long)qr1 * DIM + d) = *(unsigned*)&h;
        }
    }
}

// ---------------- launch ----------------
extern "C" void kernel_launch(void* const* d_in, const int* in_sizes, int n_in,
                              void* d_out, int out_size)
{
    const float* hidden  = (const float*)d_in[0];
    const float* history = (const float*)d_in[1];
    const float* fc   = (const float*)d_in[2];
    const float* fs   = (const float*)d_in[3];
    const float* fch  = (const float*)d_in[4];
    const float* fsh  = (const float*)d_in[5];
    const int*   sel  = (const int*)d_in[6];
    const float* Wq = (const float*)d_in[7];
    const float* bq = (const float*)d_in[8];
    const float* Wk = (const float*)d_in[9];
    const float* bk = (const float*)d_in[10];
    const float* Wv = (const float*)d_in[11];
    const float* bv = (const float*)d_in[12];
    const float* Wo = (const float*)d_in[13];
    const float* bo = (const float*)d_in[14];
    const float* gq = (const float*)d_in[15];
    const float* gk = (const float*)d_in[16];
    float* outp = (float*)d_out;

    __half *qp, *kp, *vp, *ap;
    cudaGetSymbolAddress((void**)&qp, g_q);
    cudaGetSymbolAddress((void**)&kp, g_k);
    cudaGetSymbolAddress((void**)&vp, g_v);
    cudaGetSymbolAddress((void**)&ap, g_attn);

    cudaFuncSetAttribute(gemm_bias_f16<false, true>,
                         cudaFuncAttributeMaxDynamicSharedMemorySize, GEMM_SMEM);
    cudaFuncSetAttribute(gemm_bias_f16<true, false>,
                         cudaFuncAttributeMaxDynamicSharedMemorySize, GEMM_SMEM);
    cudaFuncSetAttribute(attention_kernel,
                         cudaFuncAttributeMaxDynamicSharedMemorySize, ATT_SMEM);

    gemm_bias_f16<false, true><<<dim3(12, 25), 256, GEMM_SMEM>>>(
        hidden,  Wq, bq, qp, QTOT, DIM, DIM, nullptr);
    gemm_bias_f16<false, true><<<dim3(12, 98), 256, GEMM_SMEM>>>(
        history, Wk, bk, kp, KTOT, DIM, DIM, sel);
    gemm_bias_f16<false, true><<<dim3(12, 98), 256, GEMM_SMEM>>>(
        history, Wv, bv, vp, KTOT, DIM, DIM, sel);
    rmsnorm_rope_kernel<<<QTOT, 384>>>(qp, gq, fc, fs, nullptr);
    rmsnorm_rope_kernel<<<KTOT, 384>>>(kp, gk, fch, fsh, sel);
    attention_kernel<<<dim3(13, TQ, HEADS), 256, ATT_SMEM>>>(qp, kp, vp, sel, ap);
    gemm_bias_f16<true, false><<<dim3(12, 25), 256, GEMM_SMEM>>>(
        ap, Wo, bo, outp, QTOT, DIM, DIM, nullptr);
}

// round 10
// speedup vs baseline: 2.0601x; 1.0184x over previous
#include <cuda_runtime.h>
#include <cuda_fp16.h>
#include <cstdint>

#define HW    1560
#define TQ    2
#define QTOT  3120
#define KTOT  12480
#define HEADS 12
#define DH    128
#define DIM   1536

// ---------------- scratch (device globals; no allocation allowed) ----------------
__device__ __half g_q[QTOT * DIM];
__device__ __half g_k[KTOT * DIM];
__device__ __half g_v[KTOT * DIM];
__device__ __half g_attn[QTOT * DIM];
__device__ __half g_hid[QTOT * DIM];       // hidden_states in fp16
__device__ __half g_his[KTOT * DIM];       // history_states in fp16 (sel-gated rows)
__device__ __half g_wq[DIM * DIM];
__device__ __half g_wk[DIM * DIM];
__device__ __half g_wv[DIM * DIM];
__device__ __half g_wo[DIM * DIM];

// ---------------- helpers ----------------
__device__ __forceinline__ void mma_f16(float* d, const unsigned* a, unsigned b0, unsigned b1) {
    asm volatile(
        "mma.sync.aligned.m16n8k16.row.col.f32.f16.f16.f32 "
        "{%0,%1,%2,%3}, {%4,%5,%6,%7}, {%8,%9}, {%0,%1,%2,%3};"
        : "+f"(d[0]), "+f"(d[1]), "+f"(d[2]), "+f"(d[3])
        : "r"(a[0]), "r"(a[1]), "r"(a[2]), "r"(a[3]), "r"(b0), "r"(b1));
}

__device__ __forceinline__ uint32_t smem_u32(const void* p) {
    uint32_t a;
    asm("{ .reg .u64 t; cvta.to.shared.u64 t, %1; cvt.u32.u64 %0, t; }" : "=r"(a) : "l"(p));
    return a;
}

__device__ __forceinline__ void ldsm_x4(unsigned* r, uint32_t addr) {
    asm volatile("ldmatrix.sync.aligned.m8n8.x4.shared.b16 {%0,%1,%2,%3}, [%4];"
                 : "=r"(r[0]), "=r"(r[1]), "=r"(r[2]), "=r"(r[3]) : "r"(addr));
}

__device__ __forceinline__ uint2 f4_to_h4(float4 v) {
    __half2 h0 = __float22half2_rn(make_float2(v.x, v.y));
    __half2 h1 = __float22half2_rn(make_float2(v.z, v.w));
    uint2 r;
    r.x = *(unsigned*)&h0;
    r.y = *(unsigned*)&h1;
    return r;
}

__device__ __forceinline__ bool block_needed(int b, const int* __restrict__ sel) {
    return (sel[0] == b) | (sel[1] == b) | (sel[2] == b) | (sel[3] == b);
}

// ---------------- one-time fp32 -> fp16 conversion (row = 1536 elems) ----------------
// grid = rows, 192 threads x 8 elems. Same __float2half_rn rounding the GEMM
// producers used before -> arithmetic bit-identical.
__global__ __launch_bounds__(192) void cvt_rows_f16(
    const float* __restrict__ src, __half* __restrict__ dst,
    const int* __restrict__ sel)
{
    const int row = blockIdx.x;
    if (sel && !block_needed(row / HW, sel)) return;
    const int c = threadIdx.x * 8;
    const float* s = src + (long)row * DIM + c;
    float4 f0 = *(const float4*)s;
    float4 f1 = *(const float4*)(s + 4);
    uint2 h0 = f4_to_h4(f0), h1 = f4_to_h4(f1);
    *(uint4*)(dst + (long)row * DIM + c) = make_uint4(h0.x, h0.y, h1.x, h1.y);
}

// ---------------- GEMM: C[M,N] = A[M,K] @ W[N,K]^T + bias[N]  (all-fp16 operands) -----------
// block tile 128x128x32, 256 threads = 8 warps (2M x 4N), warp tile 64x32.
// ldmatrix fragment loads; ping-pong double-buffered smem; 2 CTAs/SM.
#define GEMM_STAGE_H (128 * 40)
#define GEMM_SMEM    (2 * 2 * GEMM_STAGE_H * 2)   // 40960 bytes

template <bool OUT_HALF>
__global__ __launch_bounds__(256, 2) void gemm_bias_f16(
    const __half* __restrict__ A, const __half* __restrict__ W,
    const float* __restrict__ bias, void* __restrict__ Cv,
    int M, int N, int K, const int* __restrict__ sel)
{
    extern __shared__ __half gh[];
    float*  Cf = (float*)Cv;
    __half* Ch = (__half*)Cv;

    const int bm = blockIdx.y * 128, bn = blockIdx.x * 128;

    if (sel) {
        int b0 = bm / HW;
        int b1 = (bm + 127) / HW;
        if (!block_needed(b0, sel) && !block_needed(b1, sel)) return;
    }

    const int tid  = threadIdx.x;
    const int warp = tid >> 5, lane = tid & 31;
    const int g = lane >> 2, t4 = lane & 3;
    const int wm = warp >> 2, wn = warp & 3;

    float acc[4][4][4] = {};

    // fp16 producer indexing: 16B = 8 halves; 256 thr cover 64 rows x 32 cols per pass
    const int lc2 = (tid & 3) * 8;
    const int lr2 = tid >> 2;       // 0..63, rows lr2, lr2+64

    // ldmatrix per-lane addressing
    const int i8 = lane >> 3, r8 = lane & 7;
    const int a_row = (i8 & 1) * 8 + r8;
    const int a_ko  = (i8 >> 1) * 8;
    const uint32_t gh_b = smem_u32(gh);
    uint32_t aoff[4], boff[2];
    #pragma unroll
    for (int mt = 0; mt < 4; mt++)
        aoff[mt] = ((wm * 64 + mt * 16 + a_row) * 40 + a_ko) * 2;
    #pragma unroll
    for (int np = 0; np < 2; np++) {
        int b_row = (i8 >> 1) * 8 + r8;
        int b_ko  = (i8 & 1) * 8;
        boff[np] = ((wn * 32 + np * 16 + b_row) * 40 + b_ko) * 2;
    }

    uint4 aH[2], wH[2];
    const uint4 z4 = make_uint4(0u, 0u, 0u, 0u);

    // prefetch k-tile 0
    #pragma unroll
    for (int i = 0; i < 2; i++) {
        int row = lr2 + 64 * i;
        long ar = bm + row;
        aH[i] = (ar < M) ? *(const uint4*)(A + ar * (long)K + lc2) : z4;
        wH[i] = *(const uint4*)(W + (long)(bn + row) * K + lc2);
    }

    // prime stage 0
    {
        __half* As = gh;
        __half* Ws = gh + GEMM_STAGE_H;
        #pragma unroll
        for (int i = 0; i < 2; i++) {
            int row = lr2 + 64 * i;
            *(uint4*)&As[row * 40 + lc2] = aH[i];
            *(uint4*)&Ws[row * 40 + lc2] = wH[i];
        }
    }
    __syncthreads();

    const int KT = K >> 5;
    for (int kt = 0; kt < KT; kt++) {
        const uint32_t As_b = gh_b + (kt & 1) * (4 * GEMM_STAGE_H);  // bytes
        const uint32_t Ws_b = As_b + 2 * GEMM_STAGE_H;

        if (kt + 1 < KT) {
            int k0 = (kt + 1) << 5;
            #pragma unroll
            for (int i = 0; i < 2; i++) {
                int row = lr2 + 64 * i;
                long ar = bm + row;
                aH[i] = (ar < M) ? *(const uint4*)(A + ar * (long)K + k0 + lc2) : z4;
                wH[i] = *(const uint4*)(W + (long)(bn + row) * K + k0 + lc2);
            }
        }

        #pragma unroll
        for (int kk = 0; kk < 2; kk++) {
            const uint32_t kB = kk * 32;
            unsigned a[4][4], b[2][4];
            #pragma unroll
            for (int mt = 0; mt < 4; mt++) ldsm_x4(a[mt], As_b + aoff[mt] + kB);
            #pragma unroll
            for (int np = 0; np < 2; np++) ldsm_x4(b[np], Ws_b + boff[np] + kB);
            #pragma unroll
            for (int nt = 0; nt < 4; nt++) {
                unsigned b0 = b[nt >> 1][(nt & 1) * 2];
                unsigned b1 = b[nt >> 1][(nt & 1) * 2 + 1];
                #pragma unroll
                for (int mt = 0; mt < 4; mt++)
                    mma_f16(acc[mt][nt], a[mt], b0, b1);
            }
        }

        if (kt + 1 < KT) {
            __half* Asn = gh + ((kt + 1) & 1) * 2 * GEMM_STAGE_H;
            __half* Wsn = Asn + GEMM_STAGE_H;
            #pragma unroll
            for (int i = 0; i < 2; i++) {
                int row = lr2 + 64 * i;
                *(uint4*)&Asn[row * 40 + lc2] = aH[i];
                *(uint4*)&Wsn[row * 40 + lc2] = wH[i];
            }
        }
        __syncthreads();
    }

    #pragma unroll
    for (int mt = 0; mt < 4; mt++) {
        int r = bm + wm * 64 + mt * 16 + g;
        #pragma unroll
        for (int nt = 0; nt < 4; nt++) {
            int c = bn + wn * 32 + nt * 8 + t4 * 2;
            float b0 = bias[c], b1 = bias[c + 1];
            if (OUT_HALF) {
                if (r < M) {
                    __half2 h = __floats2half2_rn(acc[mt][nt][0] + b0, acc[mt][nt][1] + b1);
                    *(unsigned*)(Ch + (long)r * N + c) = *(unsigned*)&h;
                }
                if (r + 8 < M) {
                    __half2 h = __floats2half2_rn(acc[mt][nt][2] + b0, acc[mt][nt][3] + b1);
                    *(unsigned*)(Ch + (long)(r + 8) * N + c) = *(unsigned*)&h;
                }
            } else {
                if (r < M)
                    *(float2*)(Cf + (long)r * N + c) =
                        make_float2(acc[mt][nt][0] + b0, acc[mt][nt][1] + b1);
                if (r + 8 < M)
                    *(float2*)(Cf + (long)(r + 8) * N + c) =
                        make_float2(acc[mt][nt][2] + b0, acc[mt][nt][3] + b1);
            }
        }
    }
}

// ---------------- fused RMSNorm + RoPE (in-place on fp16 buffer, one row per CTA) -------------
__global__ __launch_bounds__(384) void rmsnorm_rope_kernel(
    __half* __restrict__ x, const float* __restrict__ gamma,
    const float* __restrict__ fc, const float* __restrict__ fs,
    const int* __restrict__ sel)
{
    __shared__ float red[12];
    __shared__ float rinv_s;
    const int row = blockIdx.x, tid = threadIdx.x;

    if (sel && !block_needed(row / HW, sel)) return;

    uint2 u = *(uint2*)(x + (long)row * DIM + tid * 4);
    __half2 h01 = *(__half2*)&u.x;
    __half2 h23 = *(__half2*)&u.y;
    float2 f01 = __half22float2(h01);
    float2 f23 = __half22float2(h23);

    float ss = f01.x * f01.x + f01.y * f01.y + f23.x * f23.x + f23.y * f23.y;
    #pragma unroll
    for (int s = 16; s > 0; s >>= 1) ss += __shfl_xor_sync(0xffffffffu, ss, s);
    if ((tid & 31) == 0) red[tid >> 5] = ss;
    __syncthreads();
    if (tid < 32) {
        float t = (tid < 12) ? red[tid] : 0.f;
        #pragma unroll
        for (int s = 16; s > 0; s >>= 1) t += __shfl_xor_sync(0xffffffffu, t, s);
        if (tid == 0) rinv_s = rsqrtf(t * (1.0f / DIM) + 1e-5f);
    }
    __syncthreads();
    float r = rinv_s;

    float4 g4 = *(const float4*)(gamma + tid * 4);
    float x0 = f01.x * r * g4.x, x1 = f01.y * r * g4.y;
    float x2 = f23.x * r * g4.z, x3 = f23.y * r * g4.w;

    int hd = (tid * 4) & (DH - 1);
    float4 c4 = *(const float4*)(fc + (long)row * DH + hd);
    float4 s4 = *(const float4*)(fs + (long)row * DH + hd);
    float o0 = x0 * c4.x - x1 * s4.y;
    float o1 = x0 * s4.y + x1 * c4.x;
    float o2 = x2 * c4.z - x3 * s4.w;
    float o3 = x2 * s4.w + x3 * c4.z;

    __half2 ho01 = __floats2half2_rn(o0, o1);
    __half2 ho23 = __floats2half2_rn(o2, o3);
    *(uint2*)(x + (long)row * DIM + tid * 4) =
        make_uint2(*(unsigned*)&ho01, *(unsigned*)&ho23);
}

// ---------------- fused block-sparse attention (register-P, all-fp16, ldmatrix QK) ------------
#define AQ_OFF  0                        // half  [128][136]  34816 B
#define AK_OFF  34816                    // half  [64][136]   17408 B
#define AV_OFF  52224                    // uint  [32 pairs][136]  17408 B
#define ATT_SMEM 69632

__global__ __launch_bounds__(256, 2) void attention_kernel(
    const __half* __restrict__ q, const __half* __restrict__ k,
    const __half* __restrict__ v, const int* __restrict__ sel,
    __half* __restrict__ out)
{
    extern __shared__ char asm_[];
    __half*   Qh = (__half*)(asm_ + AQ_OFF);
    __half*   Kh = (__half*)(asm_ + AK_OFF);
    unsigned* Vp = (unsigned*)(asm_ + AV_OFF);

    const int qb = blockIdx.x, t = blockIdx.y, h = blockIdx.z;
    const int tid = threadIdx.x, warp = tid >> 5, lane = tid & 31;
    const int g = lane >> 2, t4 = lane & 3;

    const int i8 = lane >> 3, r8 = lane & 7;
    const uint32_t Qh_b = smem_u32(asm_) + AQ_OFF;
    const uint32_t Kh_b = smem_u32(asm_) + AK_OFF;
    const uint32_t qoff = ((warp * 16 + (i8 & 1) * 8 + r8) * 136 + (i8 >> 1) * 8) * 2;
    uint32_t koff_[4];
    #pragma unroll
    for (int np = 0; np < 4; np++)
        koff_[np] = ((np * 16 + (i8 >> 1) * 8 + r8) * 136 + (i8 & 1) * 8) * 2;

    const uint4 z4 = make_uint4(0u, 0u, 0u, 0u);

    const __half* qbase = q + (long)(t * HW) * DIM + (long)h * DH;
    {
        const int c8 = (tid & 15) * 8;
        const int lr0 = tid >> 4;
        #pragma unroll
        for (int i = 0; i < 8; i++) {
            int r = lr0 + i * 16;
            int qr = qb * 128 + r;
            uint4 val = (qr < HW) ? *(const uint4*)(qbase + (long)qr * DIM + c8) : z4;
            *(uint4*)&Qh[r * 136 + c8] = val;
        }
    }

    float oacc[16][4] = {};
    float rp0 = 0.f, rp1 = 0.f;

    int s0 = sel[t * 2 + 0]; if (s0 < 0) s0 = 0;
    int s1 = sel[t * 2 + 1];
    int nb = (s1 >= 0) ? 2 : 1;

    __syncthreads();

    const float SC   = 0.08838834764831843f * 1.4426950408889634f;
    const float OFFL = 4.0f * 1.4426950408889634f;

    for (int bi = 0; bi < nb; bi++) {
        int blk = (bi == 0) ? s0 : s1;
        const __half* kbp = k + (long)blk * HW * DIM + (long)h * DH;
        const __half* vbp = v + (long)blk * HW * DIM + (long)h * DH;

        for (int n0 = 0; n0 < HW; n0 += 64) {
            {
                const int c8 = (tid & 15) * 8;
                const int lr0 = tid >> 4;
                #pragma unroll
                for (int i = 0; i < 4; i++) {
                    int r = lr0 + i * 16;
                    int kr = n0 + r;
                    uint4 kv = (kr < HW) ? *(const uint4*)(kbp + (long)kr * DIM + c8) : z4;
                    *(uint4*)&Kh[r * 136 + c8] = kv;
                }
            }
            #pragma unroll
            for (int i = 0; i < 2; i++) {
                int idx = i * 256 + tid;
                int p = idx >> 4;
                int dc = (idx & 15) * 8;
                int kr0 = n0 + 2 * p;
                uint4 u0 = (kr0 < HW)     ? *(const uint4*)(vbp + (long)kr0 * DIM + dc) : z4;
                uint4 u1 = (kr0 + 1 < HW) ? *(const uint4*)(vbp + (long)(kr0 + 1) * DIM + dc) : z4;
                const __half* a0 = (const __half*)&u0;
                const __half* a1 = (const __half*)&u1;
                unsigned o[8];
                #pragma unroll
                for (int j = 0; j < 8; j++) {
                    __half2 hj = __halves2half2(a0[j], a1[j]);
                    o[j] = *(unsigned*)&hj;
                }
                *(uint4*)&Vp[p * 136 + dc]     = make_uint4(o[0], o[1], o[2], o[3]);
                *(uint4*)&Vp[p * 136 + dc + 4] = make_uint4(o[4], o[5], o[6], o[7]);
            }
            __syncthreads();

            float sacc[8][4] = {};
            #pragma unroll
            for (int ks = 0; ks < 8; ks++) {
                const uint32_t kB = ks * 32;
                unsigned a[4], b[4][4];
                ldsm_x4(a, Qh_b + qoff + kB);
                #pragma unroll
                for (int np = 0; np < 4; np++) ldsm_x4(b[np], Kh_b + koff_[np] + kB);
                #pragma unroll
                for (int nt = 0; nt < 8; nt++) {
                    unsigned b0 = b[nt >> 1][(nt & 1) * 2];
                    unsigned b1 = b[nt >> 1][(nt & 1) * 2 + 1];
                    mma_f16(sacc[nt], a, b0, b1);
                }
            }

            unsigned ap[4][4];
            #pragma unroll
            for (int nt = 0; nt < 8; nt++) {
                int cn = nt * 8 + 2 * t4;
                bool m0 = (n0 + cn) < HW, m1 = (n0 + cn + 1) < HW;
                float p0 = m0 ? exp2f(fmaf(sacc[nt][0], SC, -OFFL)) : 0.f;
                float p1 = m1 ? exp2f(fmaf(sacc[nt][1], SC, -OFFL)) : 0.f;
                float p2 = m0 ? exp2f(fmaf(sacc[nt][2], SC, -OFFL)) : 0.f;
                float p3 = m1 ? exp2f(fmaf(sacc[nt][3], SC, -OFFL)) : 0.f;
                rp0 += p0 + p1;
                rp1 += p2 + p3;
                __half2 h01 = __floats2half2_rn(p0, p1);
                __half2 h23 = __floats2half2_rn(p2, p3);
                ap[nt >> 1][(nt & 1) * 2 + 0] = *(unsigned*)&h01;
                ap[nt >> 1][(nt & 1) * 2 + 1] = *(unsigned*)&h23;
            }

            #pragma unroll
            for (int kp = 0; kp < 4; kp++) {
                #pragma unroll
                for (int nt = 0; nt < 16; nt++) {
                    unsigned b0 = Vp[(kp * 8 + t4) * 136 + nt * 8 + g];
                    unsigned b1 = Vp[(kp * 8 + 4 + t4) * 136 + nt * 8 + g];
                    mma_f16(oacc[nt], ap[kp], b0, b1);
                }
            }
            __syncthreads();
        }
    }

    rp0 += __shfl_xor_sync(0xffffffffu, rp0, 1);
    rp0 += __shfl_xor_sync(0xffffffffu, rp0, 2);
    rp1 += __shfl_xor_sync(0xffffffffu, rp1, 1);
    rp1 += __shfl_xor_sync(0xffffffffu, rp1, 2);
    float inv0 = 1.f / rp0, inv1 = 1.f / rp1;

    __half* obase = out + (long)(t * HW) * DIM + h * DH;
    int qr0 = qb * 128 + warp * 16 + g, qr1 = qr0 + 8;
    #pragma unroll
    for (int nt = 0; nt < 16; nt++) {
        int d = nt * 8 + 2 * t4;
        if (qr0 < HW) {
            __half2 h = __floats2half2_rn(oacc[nt][0] * inv0, oacc[nt][1] * inv0);
            *(unsigned*)(obase + (long)qr0 * DIM + d) = *(unsigned*)&h;
        }
        if (qr1 < HW) {
            __half2 h = __floats2half2_rn(oacc[nt][2] * inv1, oacc[nt][3] * inv1);
            *(unsigned*)(obase + (long)qr1 * DIM + d) = *(unsigned*)&h;
        }
    }
}

// ---------------- launch ----------------
extern "C" void kernel_launch(void* const* d_in, const int* in_sizes, int n_in,
                              void* d_out, int out_size)
{
    const float* hidden  = (const float*)d_in[0];
    const float* history = (const float*)d_in[1];
    const float* fc   = (const float*)d_in[2];
    const float* fs   = (const float*)d_in[3];
    const float* fch  = (const float*)d_in[4];
    const float* fsh  = (const float*)d_in[5];
    const int*   sel  = (const int*)d_in[6];
    const float* Wq = (const float*)d_in[7];
    const float* bq = (const float*)d_in[8];
    const float* Wk = (const float*)d_in[9];
    const float* bk = (const float*)d_in[10];
    const float* Wv = (const float*)d_in[11];
    const float* bv = (const float*)d_in[12];
    const float* Wo = (const float*)d_in[13];
    const float* bo = (const float*)d_in[14];
    const float* gq = (const float*)d_in[15];
    const float* gk = (const float*)d_in[16];
    float* outp = (float*)d_out;

    __half *qp, *kp, *vp, *ap, *hidh, *hish, *wqh, *wkh, *wvh, *woh;
    cudaGetSymbolAddress((void**)&qp, g_q);
    cudaGetSymbolAddress((void**)&kp, g_k);
    cudaGetSymbolAddress((void**)&vp, g_v);
    cudaGetSymbolAddress((void**)&ap, g_attn);
    cudaGetSymbolAddress((void**)&hidh, g_hid);
    cudaGetSymbolAddress((void**)&hish, g_his);
    cudaGetSymbolAddress((void**)&wqh, g_wq);
    cudaGetSymbolAddress((void**)&wkh, g_wk);
    cudaGetSymbolAddress((void**)&wvh, g_wv);
    cudaGetSymbolAddress((void**)&woh, g_wo);

    cudaFuncSetAttribute(gemm_bias_f16<true>,
                         cudaFuncAttributeMaxDynamicSharedMemorySize, GEMM_SMEM);
    cudaFuncSetAttribute(gemm_bias_f16<false>,
                         cudaFuncAttributeMaxDynamicSharedMemorySize, GEMM_SMEM);
    cudaFuncSetAttribute(attention_kernel,
                         cudaFuncAttributeMaxDynamicSharedMemorySize, ATT_SMEM);

    // one-time fp16 conversions (same rounding the GEMM producers used before)
    cvt_rows_f16<<<DIM, 192>>>(Wq, wqh, nullptr);
    cvt_rows_f16<<<DIM, 192>>>(Wk, wkh, nullptr);
    cvt_rows_f16<<<DIM, 192>>>(Wv, wvh, nullptr);
    cvt_rows_f16<<<DIM, 192>>>(Wo, woh, nullptr);
    cvt_rows_f16<<<QTOT, 192>>>(hidden, hidh, nullptr);
    cvt_rows_f16<<<KTOT, 192>>>(history, hish, sel);

    gemm_bias_f16<true><<<dim3(12, 25), 256, GEMM_SMEM>>>(
        hidh, wqh, bq, qp, QTOT, DIM, DIM, nullptr);
    gemm_bias_f16<true><<<dim3(12, 98), 256, GEMM_SMEM>>>(
        hish, wkh, bk, kp, KTOT, DIM, DIM, sel);
    gemm_bias_f16<true><<<dim3(12, 98), 256, GEMM_SMEM>>>(
        hish, wvh, bv, vp, KTOT, DIM, DIM, sel);
    rmsnorm_rope_kernel<<<QTOT, 384>>>(qp, gq, fc, fs, nullptr);
    rmsnorm_rope_kernel<<<KTOT, 384>>>(kp, gk, fch, fsh, sel);
    attention_kernel<<<dim3(13, TQ, HEADS), 256, ATT_SMEM>>>(qp, kp, vp, sel, ap);
    gemm_bias_f16<false><<<dim3(12, 25), 256, GEMM_SMEM>>>(
        ap, woh, bo, outp, QTOT, DIM, DIM, nullptr);
}